// round 1
// baseline (speedup 1.0000x reference)
#include <cuda_runtime.h>
#include <cstdint>
#include <math.h>

#define N_NODES 20000
#define N_EDGES 200000
#define N_GRAPHS 128
#define IN_DIM 256
#define HID 512
#define HEADS 8
#define CH 64
#define LAT 256
#define NEG_SLOPE 0.2f
#define BN_EPS 1e-5f

// ---------------- scratch (static device globals; no allocation) ----------------
__device__ __align__(16) float d_xl[(size_t)N_NODES * HID];
__device__ __align__(16) float d_xr[(size_t)N_NODES * HID];
__device__ __align__(16) float d_h [(size_t)N_NODES * HID];
__device__ __align__(16) float d_logits[(size_t)N_EDGES * HEADS];
__device__ int   d_deg[N_NODES];
__device__ int   d_off[N_NODES + 1];
__device__ int   d_cursor[N_NODES];
__device__ int   d_csr[N_EDGES];
__device__ __align__(16) float d_pool[N_GRAPHS * HID];

// ---------------- small utility kernels ----------------
__global__ void zero_int_kernel(int* p, int n) {
    int i = blockIdx.x * blockDim.x + threadIdx.x;
    if (i < n) p[i] = 0;
}
__global__ void zero_float_kernel(float* p, int n) {
    int i = blockIdx.x * blockDim.x + threadIdx.x;
    if (i < n) p[i] = 0.0f;
}

__global__ void hist_kernel(const int* __restrict__ dst) {
    int e = blockIdx.x * blockDim.x + threadIdx.x;
    if (e < N_EDGES) atomicAdd(&d_deg[dst[e]], 1);
}

// single-block exclusive scan of d_deg -> d_off (20000 elems, 1024 thr x 20 items)
__global__ void scan_kernel() {
    __shared__ int sh[1024];
    const int ITEMS = 20;
    int t = threadIdx.x;
    int base = t * ITEMS;
    int local[ITEMS];
    int s = 0;
#pragma unroll
    for (int i = 0; i < ITEMS; i++) {
        int idx = base + i;
        int v = (idx < N_NODES) ? d_deg[idx] : 0;
        local[i] = s;
        s += v;
    }
    sh[t] = s;
    __syncthreads();
    // Hillis-Steele inclusive scan over 1024 partial sums
    for (int off = 1; off < 1024; off <<= 1) {
        int v = (t >= off) ? sh[t - off] : 0;
        __syncthreads();
        sh[t] += v;
        __syncthreads();
    }
    int prev = (t > 0) ? sh[t - 1] : 0;
#pragma unroll
    for (int i = 0; i < ITEMS; i++) {
        int idx = base + i;
        if (idx < N_NODES) d_off[idx] = prev + local[i];
    }
    if (t == 1023) d_off[N_NODES] = sh[1023];
}

__global__ void cursor_kernel() {
    int n = blockIdx.x * blockDim.x + threadIdx.x;
    if (n < N_NODES) d_cursor[n] = d_off[n];
}

__global__ void scatter_kernel(const int* __restrict__ dst) {
    int e = blockIdx.x * blockDim.x + threadIdx.x;
    if (e < N_EDGES) {
        int p = atomicAdd(&d_cursor[dst[e]], 1);
        d_csr[p] = e;
    }
}

// ---------------- SGEMM: C[N,512] = A[N,K] @ B[K,512] + bias ----------------
// 128x128 tile, BK=8, 256 threads, 8x8 per-thread register tile.
#define BM 128
#define BN 128
#define BK 8
#define TM 8
#define TN 8

__global__ __launch_bounds__(256) void sgemm_bias_kernel(
    const float* __restrict__ A, const float* __restrict__ B,
    const float* __restrict__ bias, float* __restrict__ C,
    int N, int K)
{
    const int M = HID;  // 512
    __shared__ float As[BK][BM];
    __shared__ float Bs[BK][BN];

    int tid = threadIdx.x;
    int tx = tid % 16;        // col group
    int ty = tid / 16;        // row group
    int rowBase = blockIdx.y * BM;
    int colBase = blockIdx.x * BN;

    float acc[TM][TN];
#pragma unroll
    for (int i = 0; i < TM; i++)
#pragma unroll
        for (int j = 0; j < TN; j++) acc[i][j] = 0.0f;

    // A-tile load mapping: 128 rows x 8 cols = 256 float4 (2 per row)
    int arow = tid >> 1;
    int acol = (tid & 1) * 4;
    // B-tile load mapping: 8 rows x 128 cols = 256 float4
    int brow = tid >> 5;
    int bcol = (tid & 31) * 4;

    for (int k0 = 0; k0 < K; k0 += BK) {
        float4 av = make_float4(0.f, 0.f, 0.f, 0.f);
        int gr = rowBase + arow;
        if (gr < N) av = *(const float4*)(A + (size_t)gr * K + k0 + acol);
        As[acol + 0][arow] = av.x;
        As[acol + 1][arow] = av.y;
        As[acol + 2][arow] = av.z;
        As[acol + 3][arow] = av.w;

        float4 bv = *(const float4*)(B + (size_t)(k0 + brow) * M + colBase + bcol);
        *(float4*)&Bs[brow][bcol] = bv;

        __syncthreads();

#pragma unroll
        for (int k = 0; k < BK; k++) {
            float ra[TM], rb[TN];
#pragma unroll
            for (int i = 0; i < TM; i++) ra[i] = As[k][ty * TM + i];
#pragma unroll
            for (int j = 0; j < TN; j++) rb[j] = Bs[k][tx * TN + j];
#pragma unroll
            for (int i = 0; i < TM; i++)
#pragma unroll
                for (int j = 0; j < TN; j++) acc[i][j] = fmaf(ra[i], rb[j], acc[i][j]);
        }
        __syncthreads();
    }

    // epilogue: += bias, store
#pragma unroll
    for (int i = 0; i < TM; i++) {
        int r = rowBase + ty * TM + i;
        if (r >= N) continue;
        int c0 = colBase + tx * TN;
#pragma unroll
        for (int j4 = 0; j4 < TN; j4 += 4) {
            float4 v;
            v.x = acc[i][j4 + 0] + bias[c0 + j4 + 0];
            v.y = acc[i][j4 + 1] + bias[c0 + j4 + 1];
            v.z = acc[i][j4 + 2] + bias[c0 + j4 + 2];
            v.w = acc[i][j4 + 3] + bias[c0 + j4 + 3];
            *(float4*)(C + (size_t)r * M + c0 + j4) = v;
        }
    }
}

// ---------------- edge logits: logits[e,h] = sum_c lrelu(xl[src]+xr[dst])*att[h,c] ----
__global__ __launch_bounds__(256) void edge_logits_kernel(
    const float* __restrict__ xl, const float* __restrict__ xr,
    const int* __restrict__ src, const int* __restrict__ dst,
    const float* __restrict__ att)
{
    int warp = (blockIdx.x * blockDim.x + threadIdx.x) >> 5;
    if (warp >= N_EDGES) return;
    int lane = threadIdx.x & 31;
    int s = src[warp];
    int d = dst[warp];
    const float* pl = xl + (size_t)s * HID;
    const float* pr = xr + (size_t)d * HID;
#pragma unroll
    for (int h = 0; h < HEADS; h++) {
        float v = 0.0f;
#pragma unroll
        for (int r = 0; r < 2; r++) {
            int c = h * CH + lane + r * 32;
            float f = pl[c] + pr[c];
            f = (f > 0.0f) ? f : NEG_SLOPE * f;
            v = fmaf(f, att[c], v);
        }
#pragma unroll
        for (int o = 16; o > 0; o >>= 1) v += __shfl_xor_sync(0xffffffffu, v, o);
        if (lane == 0) d_logits[(size_t)warp * HEADS + h] = v;
    }
}

// ---------------- node aggregate: softmax over incoming edges + weighted sum + bias + ELU
__global__ __launch_bounds__(256) void node_agg_kernel(
    const float* __restrict__ xl, const int* __restrict__ src,
    const float* __restrict__ bias, float* __restrict__ out)
{
    int node = (blockIdx.x * blockDim.x + threadIdx.x) >> 5;
    if (node >= N_NODES) return;
    int lane = threadIdx.x & 31;
    int r0 = d_off[node], r1 = d_off[node + 1];

    int h = lane & 7;   // head for reduction phase
    int q = lane >> 3;  // 4 lanes per head

    // pass 1: per-head max
    float m = -INFINITY;
    for (int i = r0 + q; i < r1; i += 4) {
        int e = d_csr[i];
        m = fmaxf(m, d_logits[(size_t)e * HEADS + h]);
    }
    m = fmaxf(m, __shfl_xor_sync(0xffffffffu, m, 8));
    m = fmaxf(m, __shfl_xor_sync(0xffffffffu, m, 16));

    // pass 2: per-head denom
    float sden = 0.0f;
    for (int i = r0 + q; i < r1; i += 4) {
        int e = d_csr[i];
        sden += __expf(d_logits[(size_t)e * HEADS + h] - m);
    }
    sden += __shfl_xor_sync(0xffffffffu, sden, 8);
    sden += __shfl_xor_sync(0xffffffffu, sden, 16);

    // redistribute for the gather phase: thread t handles dims [t*16, t*16+16) -> head t/4
    int ht = lane >> 2;
    float mh = __shfl_sync(0xffffffffu, m, ht);
    float dh = __shfl_sync(0xffffffffu, sden, ht);
    float inv = 1.0f / (dh + 1e-16f);

    float4 a0 = make_float4(0, 0, 0, 0), a1 = a0, a2 = a0, a3 = a0;
    int dbase = lane * 16;
    for (int i = r0; i < r1; i++) {
        int e = d_csr[i];
        float alpha = __expf(d_logits[(size_t)e * HEADS + ht] - mh) * inv;
        const float4* p = (const float4*)(xl + (size_t)src[e] * HID + dbase);
        float4 v0 = p[0], v1 = p[1], v2 = p[2], v3 = p[3];
        a0.x = fmaf(alpha, v0.x, a0.x); a0.y = fmaf(alpha, v0.y, a0.y);
        a0.z = fmaf(alpha, v0.z, a0.z); a0.w = fmaf(alpha, v0.w, a0.w);
        a1.x = fmaf(alpha, v1.x, a1.x); a1.y = fmaf(alpha, v1.y, a1.y);
        a1.z = fmaf(alpha, v1.z, a1.z); a1.w = fmaf(alpha, v1.w, a1.w);
        a2.x = fmaf(alpha, v2.x, a2.x); a2.y = fmaf(alpha, v2.y, a2.y);
        a2.z = fmaf(alpha, v2.z, a2.z); a2.w = fmaf(alpha, v2.w, a2.w);
        a3.x = fmaf(alpha, v3.x, a3.x); a3.y = fmaf(alpha, v3.y, a3.y);
        a3.z = fmaf(alpha, v3.z, a3.z); a3.w = fmaf(alpha, v3.w, a3.w);
    }

    // bias + ELU + store
    float* o = out + (size_t)node * HID + dbase;
    const float* b = bias + dbase;
    float tmp[16];
    tmp[0]=a0.x; tmp[1]=a0.y; tmp[2]=a0.z; tmp[3]=a0.w;
    tmp[4]=a1.x; tmp[5]=a1.y; tmp[6]=a1.z; tmp[7]=a1.w;
    tmp[8]=a2.x; tmp[9]=a2.y; tmp[10]=a2.z; tmp[11]=a2.w;
    tmp[12]=a3.x; tmp[13]=a3.y; tmp[14]=a3.z; tmp[15]=a3.w;
#pragma unroll
    for (int j4 = 0; j4 < 16; j4 += 4) {
        float4 v;
        float vx;
        vx = tmp[j4+0] + b[j4+0]; v.x = (vx > 0.f) ? vx : (expf(vx) - 1.0f);
        vx = tmp[j4+1] + b[j4+1]; v.y = (vx > 0.f) ? vx : (expf(vx) - 1.0f);
        vx = tmp[j4+2] + b[j4+2]; v.z = (vx > 0.f) ? vx : (expf(vx) - 1.0f);
        vx = tmp[j4+3] + b[j4+3]; v.w = (vx > 0.f) ? vx : (expf(vx) - 1.0f);
        *(float4*)(o + j4) = v;
    }
}

// ---------------- pooling: pool[g] += h[n] for batch[n]==g ----------------
__global__ void pool_kernel(const float* __restrict__ h, const int* __restrict__ batch) {
    int idx = blockIdx.x * blockDim.x + threadIdx.x;  // (node, dim/4)
    if (idx >= N_NODES * (HID / 4)) return;
    int n = idx >> 7;             // HID/4 = 128
    int d4 = (idx & 127) * 4;
    int g = batch[n];
    float4 v = *(const float4*)(h + (size_t)n * HID + d4);
    float* dst = d_pool + (size_t)g * HID + d4;
    atomicAdd(dst + 0, v.x);
    atomicAdd(dst + 1, v.y);
    atomicAdd(dst + 2, v.z);
    atomicAdd(dst + 3, v.w);
}

// ---------------- head: BN (eval) + FC ----------------
__global__ __launch_bounds__(256) void head_kernel(
    const float* __restrict__ gamma, const float* __restrict__ beta,
    const float* __restrict__ mean,  const float* __restrict__ var,
    const float* __restrict__ Wfc,   const float* __restrict__ bfc,
    float* __restrict__ out)
{
    int g = blockIdx.x;
    int j = threadIdx.x;  // 256 = LAT
    __shared__ float s[HID];
    for (int k = j; k < HID; k += LAT) {
        float v = d_pool[(size_t)g * HID + k];
        s[k] = (v - mean[k]) * rsqrtf(var[k] + BN_EPS) * gamma[k] + beta[k];
    }
    __syncthreads();
    float acc = bfc[j];
    for (int k = 0; k < HID; k++) acc = fmaf(s[k], Wfc[(size_t)k * LAT + j], acc);
    out[(size_t)g * LAT + j] = acc;
}

// ---------------- launch ----------------
extern "C" void kernel_launch(void* const* d_in, const int* in_sizes, int n_in,
                              void* d_out, int out_size)
{
    const float* x      = (const float*)d_in[0];
    const int*   ei     = (const int*)d_in[1];
    const int*   batch  = (const int*)d_in[2];
    const float* Wl0    = (const float*)d_in[3];
    const float* bl0    = (const float*)d_in[4];
    const float* Wr0    = (const float*)d_in[5];
    const float* br0    = (const float*)d_in[6];
    const float* att0   = (const float*)d_in[7];
    const float* bias0  = (const float*)d_in[8];
    const float* Wl1    = (const float*)d_in[9];
    const float* bl1    = (const float*)d_in[10];
    const float* Wr1    = (const float*)d_in[11];
    const float* br1    = (const float*)d_in[12];
    const float* att1   = (const float*)d_in[13];
    const float* bias1  = (const float*)d_in[14];
    const float* bn_g   = (const float*)d_in[15];
    const float* bn_b   = (const float*)d_in[16];
    const float* bn_m   = (const float*)d_in[17];
    const float* bn_v   = (const float*)d_in[18];
    const float* Wfc    = (const float*)d_in[19];
    const float* bfc    = (const float*)d_in[20];
    float* out = (float*)d_out;

    const int* src = ei;
    const int* dst = ei + N_EDGES;

    // resolve device-symbol addresses (host-side, capture-safe)
    float *p_xl, *p_xr, *p_h, *p_pool;
    int *p_deg;
    cudaGetSymbolAddress((void**)&p_xl, d_xl);
    cudaGetSymbolAddress((void**)&p_xr, d_xr);
    cudaGetSymbolAddress((void**)&p_h, d_h);
    cudaGetSymbolAddress((void**)&p_pool, d_pool);
    cudaGetSymbolAddress((void**)&p_deg, d_deg);

    // ---- CSR build (by dst) ----
    zero_int_kernel<<<(N_NODES + 255) / 256, 256>>>(p_deg, N_NODES);
    hist_kernel<<<(N_EDGES + 255) / 256, 256>>>(dst);
    scan_kernel<<<1, 1024>>>();
    cursor_kernel<<<(N_NODES + 255) / 256, 256>>>();
    scatter_kernel<<<(N_EDGES + 255) / 256, 256>>>(dst);

    zero_float_kernel<<<(N_GRAPHS * HID + 255) / 256, 256>>>(p_pool, N_GRAPHS * HID);

    dim3 gemmGrid(HID / BN, (N_NODES + BM - 1) / BM);

    // ---- layer 0 ----
    sgemm_bias_kernel<<<gemmGrid, 256>>>(x, Wl0, bl0, p_xl, N_NODES, IN_DIM);
    sgemm_bias_kernel<<<gemmGrid, 256>>>(x, Wr0, br0, p_xr, N_NODES, IN_DIM);
    edge_logits_kernel<<<(N_EDGES * 32 + 255) / 256, 256>>>(p_xl, p_xr, src, dst, att0);
    node_agg_kernel<<<(N_NODES * 32 + 255) / 256, 256>>>(p_xl, src, bias0, p_h);

    // ---- layer 1 ----
    sgemm_bias_kernel<<<gemmGrid, 256>>>(p_h, Wl1, bl1, p_xl, N_NODES, HID);
    sgemm_bias_kernel<<<gemmGrid, 256>>>(p_h, Wr1, br1, p_xr, N_NODES, HID);
    edge_logits_kernel<<<(N_EDGES * 32 + 255) / 256, 256>>>(p_xl, p_xr, src, dst, att1);
    node_agg_kernel<<<(N_NODES * 32 + 255) / 256, 256>>>(p_xl, src, bias1, p_h);

    // ---- pool + head ----
    pool_kernel<<<(N_NODES * (HID / 4) + 255) / 256, 256>>>(p_h, batch);
    head_kernel<<<N_GRAPHS, LAT>>>(bn_g, bn_b, bn_m, bn_v, Wfc, bfc, out);
}

// round 2
// speedup vs baseline: 1.9297x; 1.9297x over previous
#include <cuda_runtime.h>
#include <cstdint>
#include <math.h>

#define N_NODES 20000
#define N_EDGES 200000
#define N_GRAPHS 128
#define IN_DIM 256
#define HID 512
#define HEADS 8
#define CH 64
#define LAT 256
#define NEG_SLOPE 0.2f
#define BN_EPS 1e-5f

// ---------------- scratch (static device globals; no allocation) ----------------
__device__ __align__(16) float d_xl[(size_t)N_NODES * HID];
__device__ __align__(16) float d_xr[(size_t)N_NODES * HID];
__device__ __align__(16) float d_h [(size_t)N_NODES * HID];
__device__ __align__(16) float d_logits[(size_t)N_EDGES * HEADS];
__device__ int   d_deg[N_NODES];
__device__ int   d_off[N_NODES + 1];
__device__ int   d_cursor[N_NODES];
__device__ int   d_csr[N_EDGES];
__device__ __align__(16) float d_pool[N_GRAPHS * HID];

// ---------------- small utility kernels ----------------
__global__ void zero_int_kernel(int* p, int n) {
    int i = blockIdx.x * blockDim.x + threadIdx.x;
    if (i < n) p[i] = 0;
}
__global__ void zero_float_kernel(float* p, int n) {
    int i = blockIdx.x * blockDim.x + threadIdx.x;
    if (i < n) p[i] = 0.0f;
}

__global__ void hist_kernel(const int* __restrict__ dst) {
    int e = blockIdx.x * blockDim.x + threadIdx.x;
    if (e < N_EDGES) atomicAdd(&d_deg[dst[e]], 1);
}

// single-block exclusive scan of d_deg -> d_off (20000 elems, 1024 thr x 20 items)
__global__ void scan_kernel() {
    __shared__ int sh[1024];
    const int ITEMS = 20;
    int t = threadIdx.x;
    int base = t * ITEMS;
    int local[ITEMS];
    int s = 0;
#pragma unroll
    for (int i = 0; i < ITEMS; i++) {
        int idx = base + i;
        int v = (idx < N_NODES) ? d_deg[idx] : 0;
        local[i] = s;
        s += v;
    }
    sh[t] = s;
    __syncthreads();
    for (int off = 1; off < 1024; off <<= 1) {
        int v = (t >= off) ? sh[t - off] : 0;
        __syncthreads();
        sh[t] += v;
        __syncthreads();
    }
    int prev = (t > 0) ? sh[t - 1] : 0;
#pragma unroll
    for (int i = 0; i < ITEMS; i++) {
        int idx = base + i;
        if (idx < N_NODES) d_off[idx] = prev + local[i];
    }
    if (t == 1023) d_off[N_NODES] = sh[1023];
}

__global__ void cursor_kernel() {
    int n = blockIdx.x * blockDim.x + threadIdx.x;
    if (n < N_NODES) d_cursor[n] = d_off[n];
}

__global__ void scatter_kernel(const int* __restrict__ dst) {
    int e = blockIdx.x * blockDim.x + threadIdx.x;
    if (e < N_EDGES) {
        int p = atomicAdd(&d_cursor[dst[e]], 1);
        d_csr[p] = e;
    }
}

// ---------------- TF32 tensor-core GEMM: C[N,512] = A[N,K] @ B[K,512] + bias ----
// Block 128x128, BK=16, 128 threads (4 warps of 64x64), double-buffered smem.
// As[m][k] stride 20 floats; Bs[k][n] stride 136 floats (conflict-free frag loads).

#define GBM 128
#define GBN 128
#define GBK 16
#define ASTR 20
#define BSTR 136

__device__ __forceinline__ float f2tf32(float x) {
    float r;
    asm("cvt.rna.tf32.f32 %0, %1;" : "=f"(r) : "f"(x));
    return r;
}

__global__ __launch_bounds__(128, 2) void gemm_tf32_kernel(
    const float* __restrict__ A, const float* __restrict__ B,
    const float* __restrict__ bias, float* __restrict__ C,
    int N, int K)
{
    __shared__ float As[2][GBM * ASTR];
    __shared__ float Bs[2][GBK * BSTR];

    const int tid  = threadIdx.x;
    const int lane = tid & 31;
    const int warp = tid >> 5;
    const int wm = warp & 1;        // 0..1
    const int wn = warp >> 1;       // 0..1
    const int rowBase = blockIdx.y * GBM;
    const int colBase = blockIdx.x * GBN;

    // A gmem load mapping: m = (tid>>2) + 32*i, k = 4*(tid&3)
    const int am = tid >> 2;
    const int ak = (tid & 3) * 4;
    // B gmem load mapping: k = tid>>3, n = 4*(tid&7) + 32*i
    const int bk = tid >> 3;
    const int bn = (tid & 7) * 4;

    float stA[4][4];
    float stB[4][4];

    const int nt = K / GBK;

    float acc[4][8][4];
#pragma unroll
    for (int i = 0; i < 4; i++)
#pragma unroll
        for (int j = 0; j < 8; j++)
#pragma unroll
            for (int q = 0; q < 4; q++) acc[i][j][q] = 0.0f;

    // ---- load tile 0 into regs ----
#pragma unroll
    for (int i = 0; i < 4; i++) {
        int r = rowBase + am + 32 * i;
        float4 v = make_float4(0.f, 0.f, 0.f, 0.f);
        if (r < N) v = *(const float4*)(A + (size_t)r * K + ak);
        stA[i][0] = v.x; stA[i][1] = v.y; stA[i][2] = v.z; stA[i][3] = v.w;
        float4 w = *(const float4*)(B + (size_t)bk * HID + colBase + bn + 32 * i);
        stB[i][0] = w.x; stB[i][1] = w.y; stB[i][2] = w.z; stB[i][3] = w.w;
    }
    // ---- store tile 0 (with tf32 rounding) ----
#pragma unroll
    for (int i = 0; i < 4; i++) {
        float4 va = make_float4(f2tf32(stA[i][0]), f2tf32(stA[i][1]), f2tf32(stA[i][2]), f2tf32(stA[i][3]));
        *(float4*)&As[0][(am + 32 * i) * ASTR + ak] = va;
        float4 vb = make_float4(f2tf32(stB[i][0]), f2tf32(stB[i][1]), f2tf32(stB[i][2]), f2tf32(stB[i][3]));
        *(float4*)&Bs[0][bk * BSTR + bn + 32 * i] = vb;
    }
    __syncthreads();

    for (int t = 0; t < nt; t++) {
        int buf = t & 1;
        if (t + 1 < nt) {
            int kb = (t + 1) * GBK;
#pragma unroll
            for (int i = 0; i < 4; i++) {
                int r = rowBase + am + 32 * i;
                float4 v = make_float4(0.f, 0.f, 0.f, 0.f);
                if (r < N) v = *(const float4*)(A + (size_t)r * K + kb + ak);
                stA[i][0] = v.x; stA[i][1] = v.y; stA[i][2] = v.z; stA[i][3] = v.w;
                float4 w = *(const float4*)(B + (size_t)(kb + bk) * HID + colBase + bn + 32 * i);
                stB[i][0] = w.x; stB[i][1] = w.y; stB[i][2] = w.z; stB[i][3] = w.w;
            }
        }

#pragma unroll
        for (int kk = 0; kk < 2; kk++) {
            const int k0 = kk * 8;
            uint32_t af[4][4];
            uint32_t bf[8][2];
#pragma unroll
            for (int im = 0; im < 4; im++) {
                int rm = wm * 64 + im * 16 + (lane >> 2);
                const float* pa = &As[buf][rm * ASTR + k0 + (lane & 3)];
                af[im][0] = __float_as_uint(pa[0]);
                af[im][1] = __float_as_uint(pa[8 * ASTR]);
                af[im][2] = __float_as_uint(pa[4]);
                af[im][3] = __float_as_uint(pa[8 * ASTR + 4]);
            }
#pragma unroll
            for (int in = 0; in < 8; in++) {
                int nb = wn * 64 + in * 8 + (lane >> 2);
                const float* pb = &Bs[buf][(k0 + (lane & 3)) * BSTR + nb];
                bf[in][0] = __float_as_uint(pb[0]);
                bf[in][1] = __float_as_uint(pb[4 * BSTR]);
            }
#pragma unroll
            for (int im = 0; im < 4; im++)
#pragma unroll
                for (int in = 0; in < 8; in++) {
                    asm volatile(
                        "mma.sync.aligned.m16n8k8.row.col.f32.tf32.tf32.f32 "
                        "{%0,%1,%2,%3}, {%4,%5,%6,%7}, {%8,%9}, {%0,%1,%2,%3};"
                        : "+f"(acc[im][in][0]), "+f"(acc[im][in][1]),
                          "+f"(acc[im][in][2]), "+f"(acc[im][in][3])
                        : "r"(af[im][0]), "r"(af[im][1]), "r"(af[im][2]), "r"(af[im][3]),
                          "r"(bf[in][0]), "r"(bf[in][1]));
                }
        }

        if (t + 1 < nt) {
            int nb_ = buf ^ 1;
#pragma unroll
            for (int i = 0; i < 4; i++) {
                float4 va = make_float4(f2tf32(stA[i][0]), f2tf32(stA[i][1]), f2tf32(stA[i][2]), f2tf32(stA[i][3]));
                *(float4*)&As[nb_][(am + 32 * i) * ASTR + ak] = va;
                float4 vb = make_float4(f2tf32(stB[i][0]), f2tf32(stB[i][1]), f2tf32(stB[i][2]), f2tf32(stB[i][3]));
                *(float4*)&Bs[nb_][bk * BSTR + bn + 32 * i] = vb;
            }
        }
        __syncthreads();
    }

    // ---- epilogue: bias add + store ----
#pragma unroll
    for (int im = 0; im < 4; im++) {
        int r0 = rowBase + wm * 64 + im * 16 + (lane >> 2);
        int r1 = r0 + 8;
#pragma unroll
        for (int in = 0; in < 8; in++) {
            int c = colBase + wn * 64 + in * 8 + 2 * (lane & 3);
            float b0 = bias[c], b1 = bias[c + 1];
            if (r0 < N) {
                float2 v0 = make_float2(acc[im][in][0] + b0, acc[im][in][1] + b1);
                *(float2*)(C + (size_t)r0 * HID + c) = v0;
            }
            if (r1 < N) {
                float2 v1 = make_float2(acc[im][in][2] + b0, acc[im][in][3] + b1);
                *(float2*)(C + (size_t)r1 * HID + c) = v1;
            }
        }
    }
}

// ---------------- edge logits ----------------
__global__ __launch_bounds__(256) void edge_logits_kernel(
    const float* __restrict__ xl, const float* __restrict__ xr,
    const int* __restrict__ src, const int* __restrict__ dst,
    const float* __restrict__ att)
{
    int warp = (blockIdx.x * blockDim.x + threadIdx.x) >> 5;
    if (warp >= N_EDGES) return;
    int lane = threadIdx.x & 31;
    int s = src[warp];
    int d = dst[warp];
    const float* pl = xl + (size_t)s * HID;
    const float* pr = xr + (size_t)d * HID;
#pragma unroll
    for (int h = 0; h < HEADS; h++) {
        float v = 0.0f;
#pragma unroll
        for (int r = 0; r < 2; r++) {
            int c = h * CH + lane + r * 32;
            float f = pl[c] + pr[c];
            f = (f > 0.0f) ? f : NEG_SLOPE * f;
            v = fmaf(f, att[c], v);
        }
#pragma unroll
        for (int o = 16; o > 0; o >>= 1) v += __shfl_xor_sync(0xffffffffu, v, o);
        if (lane == 0) d_logits[(size_t)warp * HEADS + h] = v;
    }
}

// ---------------- node aggregate ----------------
__global__ __launch_bounds__(256) void node_agg_kernel(
    const float* __restrict__ xl, const int* __restrict__ src,
    const float* __restrict__ bias, float* __restrict__ out)
{
    int node = (blockIdx.x * blockDim.x + threadIdx.x) >> 5;
    if (node >= N_NODES) return;
    int lane = threadIdx.x & 31;
    int r0 = d_off[node], r1 = d_off[node + 1];

    int h = lane & 7;
    int q = lane >> 3;

    float m = -INFINITY;
    for (int i = r0 + q; i < r1; i += 4) {
        int e = d_csr[i];
        m = fmaxf(m, d_logits[(size_t)e * HEADS + h]);
    }
    m = fmaxf(m, __shfl_xor_sync(0xffffffffu, m, 8));
    m = fmaxf(m, __shfl_xor_sync(0xffffffffu, m, 16));

    float sden = 0.0f;
    for (int i = r0 + q; i < r1; i += 4) {
        int e = d_csr[i];
        sden += __expf(d_logits[(size_t)e * HEADS + h] - m);
    }
    sden += __shfl_xor_sync(0xffffffffu, sden, 8);
    sden += __shfl_xor_sync(0xffffffffu, sden, 16);

    int ht = lane >> 2;
    float mh = __shfl_sync(0xffffffffu, m, ht);
    float dh = __shfl_sync(0xffffffffu, sden, ht);
    float inv = 1.0f / (dh + 1e-16f);

    float4 a0 = make_float4(0, 0, 0, 0), a1 = a0, a2 = a0, a3 = a0;
    int dbase = lane * 16;
    for (int i = r0; i < r1; i++) {
        int e = d_csr[i];
        float alpha = __expf(d_logits[(size_t)e * HEADS + ht] - mh) * inv;
        const float4* p = (const float4*)(xl + (size_t)src[e] * HID + dbase);
        float4 v0 = p[0], v1 = p[1], v2 = p[2], v3 = p[3];
        a0.x = fmaf(alpha, v0.x, a0.x); a0.y = fmaf(alpha, v0.y, a0.y);
        a0.z = fmaf(alpha, v0.z, a0.z); a0.w = fmaf(alpha, v0.w, a0.w);
        a1.x = fmaf(alpha, v1.x, a1.x); a1.y = fmaf(alpha, v1.y, a1.y);
        a1.z = fmaf(alpha, v1.z, a1.z); a1.w = fmaf(alpha, v1.w, a1.w);
        a2.x = fmaf(alpha, v2.x, a2.x); a2.y = fmaf(alpha, v2.y, a2.y);
        a2.z = fmaf(alpha, v2.z, a2.z); a2.w = fmaf(alpha, v2.w, a2.w);
        a3.x = fmaf(alpha, v3.x, a3.x); a3.y = fmaf(alpha, v3.y, a3.y);
        a3.z = fmaf(alpha, v3.z, a3.z); a3.w = fmaf(alpha, v3.w, a3.w);
    }

    float* o = out + (size_t)node * HID + dbase;
    const float* b = bias + dbase;
    float tmp[16];
    tmp[0]=a0.x; tmp[1]=a0.y; tmp[2]=a0.z; tmp[3]=a0.w;
    tmp[4]=a1.x; tmp[5]=a1.y; tmp[6]=a1.z; tmp[7]=a1.w;
    tmp[8]=a2.x; tmp[9]=a2.y; tmp[10]=a2.z; tmp[11]=a2.w;
    tmp[12]=a3.x; tmp[13]=a3.y; tmp[14]=a3.z; tmp[15]=a3.w;
#pragma unroll
    for (int j4 = 0; j4 < 16; j4 += 4) {
        float4 v;
        float vx;
        vx = tmp[j4+0] + b[j4+0]; v.x = (vx > 0.f) ? vx : (expf(vx) - 1.0f);
        vx = tmp[j4+1] + b[j4+1]; v.y = (vx > 0.f) ? vx : (expf(vx) - 1.0f);
        vx = tmp[j4+2] + b[j4+2]; v.z = (vx > 0.f) ? vx : (expf(vx) - 1.0f);
        vx = tmp[j4+3] + b[j4+3]; v.w = (vx > 0.f) ? vx : (expf(vx) - 1.0f);
        *(float4*)(o + j4) = v;
    }
}

// ---------------- pooling ----------------
__global__ void pool_kernel(const float* __restrict__ h, const int* __restrict__ batch) {
    int idx = blockIdx.x * blockDim.x + threadIdx.x;
    if (idx >= N_NODES * (HID / 4)) return;
    int n = idx >> 7;
    int d4 = (idx & 127) * 4;
    int g = batch[n];
    float4 v = *(const float4*)(h + (size_t)n * HID + d4);
    float* dst = d_pool + (size_t)g * HID + d4;
    atomicAdd(dst + 0, v.x);
    atomicAdd(dst + 1, v.y);
    atomicAdd(dst + 2, v.z);
    atomicAdd(dst + 3, v.w);
}

// ---------------- head: BN (eval) + FC ----------------
__global__ __launch_bounds__(256) void head_kernel(
    const float* __restrict__ gamma, const float* __restrict__ beta,
    const float* __restrict__ mean,  const float* __restrict__ var,
    const float* __restrict__ Wfc,   const float* __restrict__ bfc,
    float* __restrict__ out)
{
    int g = blockIdx.x;
    int j = threadIdx.x;
    __shared__ float s[HID];
    for (int k = j; k < HID; k += LAT) {
        float v = d_pool[(size_t)g * HID + k];
        s[k] = (v - mean[k]) * rsqrtf(var[k] + BN_EPS) * gamma[k] + beta[k];
    }
    __syncthreads();
    float acc = bfc[j];
    for (int k = 0; k < HID; k++) acc = fmaf(s[k], Wfc[(size_t)k * LAT + j], acc);
    out[(size_t)g * LAT + j] = acc;
}

// ---------------- launch ----------------
extern "C" void kernel_launch(void* const* d_in, const int* in_sizes, int n_in,
                              void* d_out, int out_size)
{
    const float* x      = (const float*)d_in[0];
    const int*   ei     = (const int*)d_in[1];
    const int*   batch  = (const int*)d_in[2];
    const float* Wl0    = (const float*)d_in[3];
    const float* bl0    = (const float*)d_in[4];
    const float* Wr0    = (const float*)d_in[5];
    const float* br0    = (const float*)d_in[6];
    const float* att0   = (const float*)d_in[7];
    const float* bias0  = (const float*)d_in[8];
    const float* Wl1    = (const float*)d_in[9];
    const float* bl1    = (const float*)d_in[10];
    const float* Wr1    = (const float*)d_in[11];
    const float* br1    = (const float*)d_in[12];
    const float* att1   = (const float*)d_in[13];
    const float* bias1  = (const float*)d_in[14];
    const float* bn_g   = (const float*)d_in[15];
    const float* bn_b   = (const float*)d_in[16];
    const float* bn_m   = (const float*)d_in[17];
    const float* bn_v   = (const float*)d_in[18];
    const float* Wfc    = (const float*)d_in[19];
    const float* bfc    = (const float*)d_in[20];
    float* out = (float*)d_out;

    const int* src = ei;
    const int* dst = ei + N_EDGES;

    float *p_xl, *p_xr, *p_h, *p_pool;
    int *p_deg;
    cudaGetSymbolAddress((void**)&p_xl, d_xl);
    cudaGetSymbolAddress((void**)&p_xr, d_xr);
    cudaGetSymbolAddress((void**)&p_h, d_h);
    cudaGetSymbolAddress((void**)&p_pool, d_pool);
    cudaGetSymbolAddress((void**)&p_deg, d_deg);

    // ---- CSR build (by dst) ----
    zero_int_kernel<<<(N_NODES + 255) / 256, 256>>>(p_deg, N_NODES);
    hist_kernel<<<(N_EDGES + 255) / 256, 256>>>(dst);
    scan_kernel<<<1, 1024>>>();
    cursor_kernel<<<(N_NODES + 255) / 256, 256>>>();
    scatter_kernel<<<(N_EDGES + 255) / 256, 256>>>(dst);

    zero_float_kernel<<<(N_GRAPHS * HID + 255) / 256, 256>>>(p_pool, N_GRAPHS * HID);

    dim3 gemmGrid(HID / GBN, (N_NODES + GBM - 1) / GBM);

    // ---- layer 0 ----
    gemm_tf32_kernel<<<gemmGrid, 128>>>(x, Wl0, bl0, p_xl, N_NODES, IN_DIM);
    gemm_tf32_kernel<<<gemmGrid, 128>>>(x, Wr0, br0, p_xr, N_NODES, IN_DIM);
    edge_logits_kernel<<<(N_EDGES * 32 + 255) / 256, 256>>>(p_xl, p_xr, src, dst, att0);
    node_agg_kernel<<<(N_NODES * 32 + 255) / 256, 256>>>(p_xl, src, bias0, p_h);

    // ---- layer 1 ----
    gemm_tf32_kernel<<<gemmGrid, 128>>>(p_h, Wl1, bl1, p_xl, N_NODES, HID);
    gemm_tf32_kernel<<<gemmGrid, 128>>>(p_h, Wr1, br1, p_xr, N_NODES, HID);
    edge_logits_kernel<<<(N_EDGES * 32 + 255) / 256, 256>>>(p_xl, p_xr, src, dst, att1);
    node_agg_kernel<<<(N_NODES * 32 + 255) / 256, 256>>>(p_xl, src, bias1, p_h);

    // ---- pool + head ----
    pool_kernel<<<(N_NODES * (HID / 4) + 255) / 256, 256>>>(p_h, batch);
    head_kernel<<<N_GRAPHS, LAT>>>(bn_g, bn_b, bn_m, bn_v, Wfc, bfc, out);
}

// round 3
// speedup vs baseline: 2.3823x; 1.2346x over previous
#include <cuda_runtime.h>
#include <cuda_fp16.h>
#include <cstdint>
#include <math.h>

#define N_NODES 20000
#define N_EDGES 200000
#define N_GRAPHS 128
#define IN_DIM 256
#define HID 512
#define HEADS 8
#define CH 64
#define LAT 256
#define NEG_SLOPE 0.2f
#define BN_EPS 1e-5f

// ---------------- scratch (static device globals; no allocation) ----------------
__device__ __align__(16) float d_xl[(size_t)N_NODES * HID];
__device__ __align__(16) float d_xr[(size_t)N_NODES * HID];
__device__ __align__(16) float d_h [(size_t)N_NODES * HID];
__device__ __align__(16) __half d_ah[(size_t)N_NODES * HID];     // fp16 copy of GEMM A operand
__device__ __align__(16) __half d_wt0[(size_t)HID * HID];        // Wl^T fp16 [N=512, K]
__device__ __align__(16) __half d_wt1[(size_t)HID * HID];        // Wr^T fp16
__device__ __align__(16) float d_logits[(size_t)N_EDGES * HEADS];
__device__ int   d_deg[N_NODES];
__device__ int   d_off[N_NODES + 1];
__device__ int   d_cursor[N_NODES];
__device__ int   d_csr[N_EDGES];
__device__ int   d_goff[N_GRAPHS + 1];
__device__ __align__(16) float d_pool[N_GRAPHS * HID];

// ---------------- small utility kernels ----------------
__global__ void zero_int_kernel(int* p, int n) {
    int i = blockIdx.x * blockDim.x + threadIdx.x;
    if (i < n) p[i] = 0;
}

__global__ void hist_kernel(const int* __restrict__ dst) {
    int e = blockIdx.x * blockDim.x + threadIdx.x;
    if (e < N_EDGES) atomicAdd(&d_deg[dst[e]], 1);
}

// single-block exclusive scan of d_deg -> d_off
__global__ void scan_kernel() {
    __shared__ int sh[1024];
    const int ITEMS = 20;
    int t = threadIdx.x;
    int base = t * ITEMS;
    int local[ITEMS];
    int s = 0;
#pragma unroll
    for (int i = 0; i < ITEMS; i++) {
        int idx = base + i;
        int v = (idx < N_NODES) ? d_deg[idx] : 0;
        local[i] = s;
        s += v;
    }
    sh[t] = s;
    __syncthreads();
    for (int off = 1; off < 1024; off <<= 1) {
        int v = (t >= off) ? sh[t - off] : 0;
        __syncthreads();
        sh[t] += v;
        __syncthreads();
    }
    int prev = (t > 0) ? sh[t - 1] : 0;
#pragma unroll
    for (int i = 0; i < ITEMS; i++) {
        int idx = base + i;
        if (idx < N_NODES) d_off[idx] = prev + local[i];
    }
    if (t == 1023) d_off[N_NODES] = sh[1023];
}

__global__ void cursor_kernel() {
    int n = blockIdx.x * blockDim.x + threadIdx.x;
    if (n < N_NODES) d_cursor[n] = d_off[n];
}

__global__ void scatter_kernel(const int* __restrict__ dst) {
    int e = blockIdx.x * blockDim.x + threadIdx.x;
    if (e < N_EDGES) {
        int p = atomicAdd(&d_cursor[dst[e]], 1);
        d_csr[p] = e;
    }
}

// graph boundaries via binary search over sorted batch
__global__ void goff_kernel(const int* __restrict__ batch) {
    int g = blockIdx.x * blockDim.x + threadIdx.x;
    if (g > N_GRAPHS) return;
    int lo = 0, hi = N_NODES;
    while (lo < hi) {
        int mid = (lo + hi) >> 1;
        if (batch[mid] < g) lo = mid + 1; else hi = mid;
    }
    d_goff[g] = lo;
}

// fp32 -> fp16 (vectorized by 4)
__global__ void conv_f2h_kernel(const float* __restrict__ src, __half* __restrict__ dst, int n4) {
    int i = blockIdx.x * blockDim.x + threadIdx.x;
    if (i < n4) {
        float4 v = ((const float4*)src)[i];
        __half2* d = (__half2*)dst;
        d[i * 2 + 0] = __floats2half2_rn(v.x, v.y);
        d[i * 2 + 1] = __floats2half2_rn(v.z, v.w);
    }
}

// W[K][512] f32  ->  Wt[512][K] f16  (tiled transpose)
__global__ void wtrans_kernel(const float* __restrict__ W, __half* __restrict__ Wt, int K) {
    __shared__ float tile[32][33];
    int n0 = blockIdx.x * 32;
    int k0 = blockIdx.y * 32;
    int tx = threadIdx.x, ty = threadIdx.y;  // 32 x 8
#pragma unroll
    for (int j = 0; j < 32; j += 8)
        tile[ty + j][tx] = W[(size_t)(k0 + ty + j) * HID + n0 + tx];
    __syncthreads();
#pragma unroll
    for (int j = 0; j < 32; j += 8)
        Wt[(size_t)(n0 + ty + j) * K + k0 + tx] = __float2half_rn(tile[tx][ty + j]);
}

// ---------------- fp16 tensor-core GEMM: C[N,512] = A[N,K] @ Bt^T + bias -------
// A: fp16 [N,K] row-major. Bt: fp16 [512,K] row-major (= W^T). C: fp32.
// Block 128x128, BK=32, 128 threads (4 warps of 64x64), double-buffered.
// Smem rows stride 40 halves (20 words): conflict-free frag LDS + aligned float4 STS.

#define GBM 128
#define GBN 128
#define HBK 32
#define SSTR 40   // halves per smem row

__global__ __launch_bounds__(128, 2) void gemm_f16_kernel(
    const __half* __restrict__ A, const __half* __restrict__ Bt,
    const float* __restrict__ bias, float* __restrict__ C,
    int N, int K)
{
    __shared__ __half As[2][GBM * SSTR];
    __shared__ __half Bs[2][GBN * SSTR];

    const int tid  = threadIdx.x;
    const int lane = tid & 31;
    const int warp = tid >> 5;
    const int wm = warp & 1;
    const int wn = warp >> 1;
    const int rowBase = blockIdx.y * GBM;
    const int colBase = blockIdx.x * GBN;

    const int lr = tid >> 2;        // row within 32-row pass
    const int lc = (tid & 3) * 8;   // half offset within BK

    const int g = lane >> 2;        // mma group row
    const int q = lane & 3;

    const int nt = K / HBK;

    float acc[4][8][4];
#pragma unroll
    for (int i = 0; i < 4; i++)
#pragma unroll
        for (int j = 0; j < 8; j++)
#pragma unroll
            for (int p = 0; p < 4; p++) acc[i][j][p] = 0.0f;

    uint4 stA[4], stB[4];

    // ---- load tile 0 ----
#pragma unroll
    for (int i = 0; i < 4; i++) {
        int r = rowBase + lr + 32 * i;
        stA[i] = (r < N) ? *(const uint4*)(A + (size_t)r * K + lc)
                         : make_uint4(0u, 0u, 0u, 0u);
        int br = colBase + lr + 32 * i;
        stB[i] = *(const uint4*)(Bt + (size_t)br * K + lc);
    }
#pragma unroll
    for (int i = 0; i < 4; i++) {
        *(uint4*)&As[0][(lr + 32 * i) * SSTR + lc] = stA[i];
        *(uint4*)&Bs[0][(lr + 32 * i) * SSTR + lc] = stB[i];
    }
    __syncthreads();

    for (int t = 0; t < nt; t++) {
        int buf = t & 1;
        if (t + 1 < nt) {
            int kb = (t + 1) * HBK;
#pragma unroll
            for (int i = 0; i < 4; i++) {
                int r = rowBase + lr + 32 * i;
                stA[i] = (r < N) ? *(const uint4*)(A + (size_t)r * K + kb + lc)
                                 : make_uint4(0u, 0u, 0u, 0u);
                int br = colBase + lr + 32 * i;
                stB[i] = *(const uint4*)(Bt + (size_t)br * K + kb + lc);
            }
        }

#pragma unroll
        for (int kk = 0; kk < 2; kk++) {
            const int kh = kk * 16 + q * 2;   // half offset of this thread's k-pair
            uint32_t af[4][4];
            uint32_t bf[8][2];
#pragma unroll
            for (int im = 0; im < 4; im++) {
                int mrow = wm * 64 + im * 16 + g;
                const __half* pa = &As[buf][mrow * SSTR + kh];
                af[im][0] = *(const uint32_t*)(pa);
                af[im][1] = *(const uint32_t*)(pa + 8 * SSTR);
                af[im][2] = *(const uint32_t*)(pa + 8);
                af[im][3] = *(const uint32_t*)(pa + 8 * SSTR + 8);
            }
#pragma unroll
            for (int in = 0; in < 8; in++) {
                int nrow = wn * 64 + in * 8 + g;
                const __half* pb = &Bs[buf][nrow * SSTR + kh];
                bf[in][0] = *(const uint32_t*)(pb);
                bf[in][1] = *(const uint32_t*)(pb + 8);
            }
#pragma unroll
            for (int im = 0; im < 4; im++)
#pragma unroll
                for (int in = 0; in < 8; in++) {
                    asm volatile(
                        "mma.sync.aligned.m16n8k16.row.col.f32.f16.f16.f32 "
                        "{%0,%1,%2,%3}, {%4,%5,%6,%7}, {%8,%9}, {%0,%1,%2,%3};"
                        : "+f"(acc[im][in][0]), "+f"(acc[im][in][1]),
                          "+f"(acc[im][in][2]), "+f"(acc[im][in][3])
                        : "r"(af[im][0]), "r"(af[im][1]), "r"(af[im][2]), "r"(af[im][3]),
                          "r"(bf[in][0]), "r"(bf[in][1]));
                }
        }

        if (t + 1 < nt) {
            int nbuf = buf ^ 1;
#pragma unroll
            for (int i = 0; i < 4; i++) {
                *(uint4*)&As[nbuf][(lr + 32 * i) * SSTR + lc] = stA[i];
                *(uint4*)&Bs[nbuf][(lr + 32 * i) * SSTR + lc] = stB[i];
            }
        }
        __syncthreads();
    }

    // ---- epilogue: bias add + store ----
#pragma unroll
    for (int im = 0; im < 4; im++) {
        int r0 = rowBase + wm * 64 + im * 16 + g;
        int r1 = r0 + 8;
#pragma unroll
        for (int in = 0; in < 8; in++) {
            int c = colBase + wn * 64 + in * 8 + 2 * q;
            float b0 = bias[c], b1 = bias[c + 1];
            if (r0 < N) {
                float2 v0 = make_float2(acc[im][in][0] + b0, acc[im][in][1] + b1);
                *(float2*)(C + (size_t)r0 * HID + c) = v0;
            }
            if (r1 < N) {
                float2 v1 = make_float2(acc[im][in][2] + b0, acc[im][in][3] + b1);
                *(float2*)(C + (size_t)r1 * HID + c) = v1;
            }
        }
    }
}

// ---------------- edge logits ----------------
__global__ __launch_bounds__(256) void edge_logits_kernel(
    const float* __restrict__ xl, const float* __restrict__ xr,
    const int* __restrict__ src, const int* __restrict__ dst,
    const float* __restrict__ att)
{
    int warp = (blockIdx.x * blockDim.x + threadIdx.x) >> 5;
    if (warp >= N_EDGES) return;
    int lane = threadIdx.x & 31;
    int s = src[warp];
    int d = dst[warp];
    const float* pl = xl + (size_t)s * HID;
    const float* pr = xr + (size_t)d * HID;
#pragma unroll
    for (int h = 0; h < HEADS; h++) {
        float v = 0.0f;
#pragma unroll
        for (int r = 0; r < 2; r++) {
            int c = h * CH + lane + r * 32;
            float f = pl[c] + pr[c];
            f = (f > 0.0f) ? f : NEG_SLOPE * f;
            v = fmaf(f, att[c], v);
        }
#pragma unroll
        for (int o = 16; o > 0; o >>= 1) v += __shfl_xor_sync(0xffffffffu, v, o);
        if (lane == 0) d_logits[(size_t)warp * HEADS + h] = v;
    }
}

// ---------------- node aggregate ----------------
__global__ __launch_bounds__(256) void node_agg_kernel(
    const float* __restrict__ xl, const int* __restrict__ src,
    const float* __restrict__ bias, float* __restrict__ out)
{
    int node = (blockIdx.x * blockDim.x + threadIdx.x) >> 5;
    if (node >= N_NODES) return;
    int lane = threadIdx.x & 31;
    int r0 = d_off[node], r1 = d_off[node + 1];

    int h = lane & 7;
    int q = lane >> 3;

    float m = -INFINITY;
    for (int i = r0 + q; i < r1; i += 4) {
        int e = d_csr[i];
        m = fmaxf(m, d_logits[(size_t)e * HEADS + h]);
    }
    m = fmaxf(m, __shfl_xor_sync(0xffffffffu, m, 8));
    m = fmaxf(m, __shfl_xor_sync(0xffffffffu, m, 16));

    float sden = 0.0f;
    for (int i = r0 + q; i < r1; i += 4) {
        int e = d_csr[i];
        sden += __expf(d_logits[(size_t)e * HEADS + h] - m);
    }
    sden += __shfl_xor_sync(0xffffffffu, sden, 8);
    sden += __shfl_xor_sync(0xffffffffu, sden, 16);

    int ht = lane >> 2;
    float mh = __shfl_sync(0xffffffffu, m, ht);
    float dh = __shfl_sync(0xffffffffu, sden, ht);
    float inv = 1.0f / (dh + 1e-16f);

    float4 a0 = make_float4(0, 0, 0, 0), a1 = a0, a2 = a0, a3 = a0;
    int dbase = lane * 16;
    for (int i = r0; i < r1; i++) {
        int e = d_csr[i];
        float alpha = __expf(d_logits[(size_t)e * HEADS + ht] - mh) * inv;
        const float4* p = (const float4*)(xl + (size_t)src[e] * HID + dbase);
        float4 v0 = p[0], v1 = p[1], v2 = p[2], v3 = p[3];
        a0.x = fmaf(alpha, v0.x, a0.x); a0.y = fmaf(alpha, v0.y, a0.y);
        a0.z = fmaf(alpha, v0.z, a0.z); a0.w = fmaf(alpha, v0.w, a0.w);
        a1.x = fmaf(alpha, v1.x, a1.x); a1.y = fmaf(alpha, v1.y, a1.y);
        a1.z = fmaf(alpha, v1.z, a1.z); a1.w = fmaf(alpha, v1.w, a1.w);
        a2.x = fmaf(alpha, v2.x, a2.x); a2.y = fmaf(alpha, v2.y, a2.y);
        a2.z = fmaf(alpha, v2.z, a2.z); a2.w = fmaf(alpha, v2.w, a2.w);
        a3.x = fmaf(alpha, v3.x, a3.x); a3.y = fmaf(alpha, v3.y, a3.y);
        a3.z = fmaf(alpha, v3.z, a3.z); a3.w = fmaf(alpha, v3.w, a3.w);
    }

    float* o = out + (size_t)node * HID + dbase;
    const float* b = bias + dbase;
    float tmp[16];
    tmp[0]=a0.x; tmp[1]=a0.y; tmp[2]=a0.z; tmp[3]=a0.w;
    tmp[4]=a1.x; tmp[5]=a1.y; tmp[6]=a1.z; tmp[7]=a1.w;
    tmp[8]=a2.x; tmp[9]=a2.y; tmp[10]=a2.z; tmp[11]=a2.w;
    tmp[12]=a3.x; tmp[13]=a3.y; tmp[14]=a3.z; tmp[15]=a3.w;
#pragma unroll
    for (int j4 = 0; j4 < 16; j4 += 4) {
        float4 v;
        float vx;
        vx = tmp[j4+0] + b[j4+0]; v.x = (vx > 0.f) ? vx : (expf(vx) - 1.0f);
        vx = tmp[j4+1] + b[j4+1]; v.y = (vx > 0.f) ? vx : (expf(vx) - 1.0f);
        vx = tmp[j4+2] + b[j4+2]; v.z = (vx > 0.f) ? vx : (expf(vx) - 1.0f);
        vx = tmp[j4+3] + b[j4+3]; v.w = (vx > 0.f) ? vx : (expf(vx) - 1.0f);
        *(float4*)(o + j4) = v;
    }
}

// ---------------- pooling: segmented sum (batch is sorted) ----------------
__global__ void pool_seg_kernel(const float* __restrict__ h) {
    int g = blockIdx.x;
    int dim = blockIdx.y * 128 + threadIdx.x;
    int e = d_goff[g + 1];
    float s = 0.0f;
    for (int n = d_goff[g]; n < e; n++) s += h[(size_t)n * HID + dim];
    d_pool[g * HID + dim] = s;
}

// ---------------- head: BN (eval) + FC ----------------
__global__ __launch_bounds__(256) void head_kernel(
    const float* __restrict__ gamma, const float* __restrict__ beta,
    const float* __restrict__ mean,  const float* __restrict__ var,
    const float* __restrict__ Wfc,   const float* __restrict__ bfc,
    float* __restrict__ out)
{
    int g = blockIdx.x;
    int j = threadIdx.x;
    __shared__ float s[HID];
    for (int k = j; k < HID; k += LAT) {
        float v = d_pool[(size_t)g * HID + k];
        s[k] = (v - mean[k]) * rsqrtf(var[k] + BN_EPS) * gamma[k] + beta[k];
    }
    __syncthreads();
    float acc = bfc[j];
    for (int k = 0; k < HID; k++) acc = fmaf(s[k], Wfc[(size_t)k * LAT + j], acc);
    out[(size_t)g * LAT + j] = acc;
}

// ---------------- launch ----------------
extern "C" void kernel_launch(void* const* d_in, const int* in_sizes, int n_in,
                              void* d_out, int out_size)
{
    const float* x      = (const float*)d_in[0];
    const int*   ei     = (const int*)d_in[1];
    const int*   batch  = (const int*)d_in[2];
    const float* Wl0    = (const float*)d_in[3];
    const float* bl0    = (const float*)d_in[4];
    const float* Wr0    = (const float*)d_in[5];
    const float* br0    = (const float*)d_in[6];
    const float* att0   = (const float*)d_in[7];
    const float* bias0  = (const float*)d_in[8];
    const float* Wl1    = (const float*)d_in[9];
    const float* bl1    = (const float*)d_in[10];
    const float* Wr1    = (const float*)d_in[11];
    const float* br1    = (const float*)d_in[12];
    const float* att1   = (const float*)d_in[13];
    const float* bias1  = (const float*)d_in[14];
    const float* bn_g   = (const float*)d_in[15];
    const float* bn_b   = (const float*)d_in[16];
    const float* bn_m   = (const float*)d_in[17];
    const float* bn_v   = (const float*)d_in[18];
    const float* Wfc    = (const float*)d_in[19];
    const float* bfc    = (const float*)d_in[20];
    float* out = (float*)d_out;

    const int* src = ei;
    const int* dst = ei + N_EDGES;

    float *p_xl, *p_xr, *p_h;
    __half *p_ah, *p_wt0, *p_wt1;
    int *p_deg;
    cudaGetSymbolAddress((void**)&p_xl, d_xl);
    cudaGetSymbolAddress((void**)&p_xr, d_xr);
    cudaGetSymbolAddress((void**)&p_h, d_h);
    cudaGetSymbolAddress((void**)&p_ah, d_ah);
    cudaGetSymbolAddress((void**)&p_wt0, d_wt0);
    cudaGetSymbolAddress((void**)&p_wt1, d_wt1);
    cudaGetSymbolAddress((void**)&p_deg, d_deg);

    // ---- CSR build (by dst) + graph offsets ----
    zero_int_kernel<<<(N_NODES + 255) / 256, 256>>>(p_deg, N_NODES);
    hist_kernel<<<(N_EDGES + 255) / 256, 256>>>(dst);
    scan_kernel<<<1, 1024>>>();
    cursor_kernel<<<(N_NODES + 255) / 256, 256>>>();
    scatter_kernel<<<(N_EDGES + 255) / 256, 256>>>(dst);
    goff_kernel<<<1, 256>>>(batch);

    dim3 gemmGrid(HID / GBN, (N_NODES + GBM - 1) / GBM);
    dim3 wtB(32, 8);

    // ---- layer 0 ----
    conv_f2h_kernel<<<(N_NODES * IN_DIM / 4 + 255) / 256, 256>>>(x, p_ah, N_NODES * IN_DIM / 4);
    wtrans_kernel<<<dim3(HID / 32, IN_DIM / 32), wtB>>>(Wl0, p_wt0, IN_DIM);
    wtrans_kernel<<<dim3(HID / 32, IN_DIM / 32), wtB>>>(Wr0, p_wt1, IN_DIM);
    gemm_f16_kernel<<<gemmGrid, 128>>>(p_ah, p_wt0, bl0, p_xl, N_NODES, IN_DIM);
    gemm_f16_kernel<<<gemmGrid, 128>>>(p_ah, p_wt1, br0, p_xr, N_NODES, IN_DIM);
    edge_logits_kernel<<<(N_EDGES * 32 + 255) / 256, 256>>>(p_xl, p_xr, src, dst, att0);
    node_agg_kernel<<<(N_NODES * 32 + 255) / 256, 256>>>(p_xl, src, bias0, p_h);

    // ---- layer 1 ----
    conv_f2h_kernel<<<(N_NODES * HID / 4 + 255) / 256, 256>>>(p_h, p_ah, N_NODES * HID / 4);
    wtrans_kernel<<<dim3(HID / 32, HID / 32), wtB>>>(Wl1, p_wt0, HID);
    wtrans_kernel<<<dim3(HID / 32, HID / 32), wtB>>>(Wr1, p_wt1, HID);
    gemm_f16_kernel<<<gemmGrid, 128>>>(p_ah, p_wt0, bl1, p_xl, N_NODES, HID);
    gemm_f16_kernel<<<gemmGrid, 128>>>(p_ah, p_wt1, br1, p_xr, N_NODES, HID);
    edge_logits_kernel<<<(N_EDGES * 32 + 255) / 256, 256>>>(p_xl, p_xr, src, dst, att1);
    node_agg_kernel<<<(N_NODES * 32 + 255) / 256, 256>>>(p_xl, src, bias1, p_h);

    // ---- pool + head ----
    pool_seg_kernel<<<dim3(N_GRAPHS, HID / 128), 128>>>(p_h);
    head_kernel<<<N_GRAPHS, LAT>>>(bn_g, bn_b, bn_m, bn_v, Wfc, bfc, out);
}

// round 4
// speedup vs baseline: 3.5121x; 1.4742x over previous
#include <cuda_runtime.h>
#include <cuda_fp16.h>
#include <cstdint>
#include <math.h>

#define N_NODES 20000
#define N_EDGES 200000
#define N_GRAPHS 128
#define IN_DIM 256
#define HID 512
#define HEADS 8
#define CH 64
#define LAT 256
#define NEG_SLOPE 0.2f
#define BN_EPS 1e-5f

// ---------------- scratch (static device globals; no allocation) ----------------
__device__ __align__(16) __half d_xh [(size_t)N_NODES * HID];   // GEMM A input (x or h, fp16)
__device__ __align__(16) __half d_xlh[(size_t)N_NODES * HID];   // xl fp16
__device__ __align__(16) float  d_xr [(size_t)N_NODES * HID];   // xr fp32
__device__ __align__(16) float  d_h  [(size_t)N_NODES * HID];   // final layer-1 h (pool input)
__device__ __align__(16) __half d_wt0[(size_t)HID * HID];       // Wl^T fp16 [512, K]
__device__ __align__(16) __half d_wt1[(size_t)HID * HID];       // Wr^T fp16
__device__ int   d_deg[N_NODES];
__device__ int   d_off[N_NODES + 1];
__device__ int   d_cursor[N_NODES];
__device__ int   d_csr[N_EDGES];         // stores SRC node id, grouped by dst
__device__ int   d_goff[N_GRAPHS + 1];
__device__ __align__(16) float d_pool[N_GRAPHS * HID];

// ---------------- small utility kernels ----------------
__global__ void zero_int_kernel(int* p, int n) {
    int i = blockIdx.x * blockDim.x + threadIdx.x;
    if (i < n) p[i] = 0;
}

__global__ void hist_kernel(const int* __restrict__ dst) {
    int e = blockIdx.x * blockDim.x + threadIdx.x;
    if (e < N_EDGES) atomicAdd(&d_deg[dst[e]], 1);
}

// single-block exclusive scan of d_deg -> d_off
__global__ void scan_kernel() {
    __shared__ int sh[1024];
    const int ITEMS = 20;
    int t = threadIdx.x;
    int base = t * ITEMS;
    int local[ITEMS];
    int s = 0;
#pragma unroll
    for (int i = 0; i < ITEMS; i++) {
        int idx = base + i;
        int v = (idx < N_NODES) ? d_deg[idx] : 0;
        local[i] = s;
        s += v;
    }
    sh[t] = s;
    __syncthreads();
    for (int off = 1; off < 1024; off <<= 1) {
        int v = (t >= off) ? sh[t - off] : 0;
        __syncthreads();
        sh[t] += v;
        __syncthreads();
    }
    int prev = (t > 0) ? sh[t - 1] : 0;
#pragma unroll
    for (int i = 0; i < ITEMS; i++) {
        int idx = base + i;
        if (idx < N_NODES) d_off[idx] = prev + local[i];
    }
    if (t == 1023) d_off[N_NODES] = sh[1023];
}

__global__ void cursor_kernel() {
    int n = blockIdx.x * blockDim.x + threadIdx.x;
    if (n < N_NODES) d_cursor[n] = d_off[n];
}

__global__ void scatter_kernel(const int* __restrict__ src, const int* __restrict__ dst) {
    int e = blockIdx.x * blockDim.x + threadIdx.x;
    if (e < N_EDGES) {
        int p = atomicAdd(&d_cursor[dst[e]], 1);
        d_csr[p] = src[e];                  // store src id directly
    }
}

// graph boundaries via binary search over sorted batch
__global__ void goff_kernel(const int* __restrict__ batch) {
    int g = blockIdx.x * blockDim.x + threadIdx.x;
    if (g > N_GRAPHS) return;
    int lo = 0, hi = N_NODES;
    while (lo < hi) {
        int mid = (lo + hi) >> 1;
        if (batch[mid] < g) lo = mid + 1; else hi = mid;
    }
    d_goff[g] = lo;
}

// fp32 -> fp16 (vectorized by 4)
__global__ void conv_f2h_kernel(const float* __restrict__ src, __half* __restrict__ dst, int n4) {
    int i = blockIdx.x * blockDim.x + threadIdx.x;
    if (i < n4) {
        float4 v = ((const float4*)src)[i];
        __half2* d = (__half2*)dst;
        d[i * 2 + 0] = __floats2half2_rn(v.x, v.y);
        d[i * 2 + 1] = __floats2half2_rn(v.z, v.w);
    }
}

// W[K][512] f32  ->  Wt[512][K] f16  (tiled transpose)
__global__ void wtrans_kernel(const float* __restrict__ W, __half* __restrict__ Wt, int K) {
    __shared__ float tile[32][33];
    int n0 = blockIdx.x * 32;
    int k0 = blockIdx.y * 32;
    int tx = threadIdx.x, ty = threadIdx.y;  // 32 x 8
#pragma unroll
    for (int j = 0; j < 32; j += 8)
        tile[ty + j][tx] = W[(size_t)(k0 + ty + j) * HID + n0 + tx];
    __syncthreads();
#pragma unroll
    for (int j = 0; j < 32; j += 8)
        Wt[(size_t)(n0 + ty + j) * K + k0 + tx] = __float2half_rn(tile[tx][ty + j]);
}

// ---------------- fp16 tensor-core GEMM: C[N,512] = A[N,K] @ Bt^T + bias -------
#define GBM 128
#define GBN 128
#define HBK 32
#define SSTR 40   // halves per smem row

template <bool HALF_OUT>
__global__ __launch_bounds__(128, 2) void gemm_f16_kernel(
    const __half* __restrict__ A, const __half* __restrict__ Bt,
    const float* __restrict__ bias, void* __restrict__ Cout,
    int N, int K)
{
    __shared__ __half As[2][GBM * SSTR];
    __shared__ __half Bs[2][GBN * SSTR];

    const int tid  = threadIdx.x;
    const int lane = tid & 31;
    const int warp = tid >> 5;
    const int wm = warp & 1;
    const int wn = warp >> 1;
    const int rowBase = blockIdx.y * GBM;
    const int colBase = blockIdx.x * GBN;

    const int lr = tid >> 2;
    const int lc = (tid & 3) * 8;
    const int g = lane >> 2;
    const int q = lane & 3;
    const int nt = K / HBK;

    float acc[4][8][4];
#pragma unroll
    for (int i = 0; i < 4; i++)
#pragma unroll
        for (int j = 0; j < 8; j++)
#pragma unroll
            for (int p = 0; p < 4; p++) acc[i][j][p] = 0.0f;

    uint4 stA[4], stB[4];

#pragma unroll
    for (int i = 0; i < 4; i++) {
        int r = rowBase + lr + 32 * i;
        stA[i] = (r < N) ? *(const uint4*)(A + (size_t)r * K + lc)
                         : make_uint4(0u, 0u, 0u, 0u);
        int br = colBase + lr + 32 * i;
        stB[i] = *(const uint4*)(Bt + (size_t)br * K + lc);
    }
#pragma unroll
    for (int i = 0; i < 4; i++) {
        *(uint4*)&As[0][(lr + 32 * i) * SSTR + lc] = stA[i];
        *(uint4*)&Bs[0][(lr + 32 * i) * SSTR + lc] = stB[i];
    }
    __syncthreads();

    for (int t = 0; t < nt; t++) {
        int buf = t & 1;
        if (t + 1 < nt) {
            int kb = (t + 1) * HBK;
#pragma unroll
            for (int i = 0; i < 4; i++) {
                int r = rowBase + lr + 32 * i;
                stA[i] = (r < N) ? *(const uint4*)(A + (size_t)r * K + kb + lc)
                                 : make_uint4(0u, 0u, 0u, 0u);
                int br = colBase + lr + 32 * i;
                stB[i] = *(const uint4*)(Bt + (size_t)br * K + kb + lc);
            }
        }

#pragma unroll
        for (int kk = 0; kk < 2; kk++) {
            const int kh = kk * 16 + q * 2;
            uint32_t af[4][4];
            uint32_t bf[8][2];
#pragma unroll
            for (int im = 0; im < 4; im++) {
                int mrow = wm * 64 + im * 16 + g;
                const __half* pa = &As[buf][mrow * SSTR + kh];
                af[im][0] = *(const uint32_t*)(pa);
                af[im][1] = *(const uint32_t*)(pa + 8 * SSTR);
                af[im][2] = *(const uint32_t*)(pa + 8);
                af[im][3] = *(const uint32_t*)(pa + 8 * SSTR + 8);
            }
#pragma unroll
            for (int in = 0; in < 8; in++) {
                int nrow = wn * 64 + in * 8 + g;
                const __half* pb = &Bs[buf][nrow * SSTR + kh];
                bf[in][0] = *(const uint32_t*)(pb);
                bf[in][1] = *(const uint32_t*)(pb + 8);
            }
#pragma unroll
            for (int im = 0; im < 4; im++)
#pragma unroll
                for (int in = 0; in < 8; in++) {
                    asm volatile(
                        "mma.sync.aligned.m16n8k16.row.col.f32.f16.f16.f32 "
                        "{%0,%1,%2,%3}, {%4,%5,%6,%7}, {%8,%9}, {%0,%1,%2,%3};"
                        : "+f"(acc[im][in][0]), "+f"(acc[im][in][1]),
                          "+f"(acc[im][in][2]), "+f"(acc[im][in][3])
                        : "r"(af[im][0]), "r"(af[im][1]), "r"(af[im][2]), "r"(af[im][3]),
                          "r"(bf[in][0]), "r"(bf[in][1]));
                }
        }

        if (t + 1 < nt) {
            int nbuf = buf ^ 1;
#pragma unroll
            for (int i = 0; i < 4; i++) {
                *(uint4*)&As[nbuf][(lr + 32 * i) * SSTR + lc] = stA[i];
                *(uint4*)&Bs[nbuf][(lr + 32 * i) * SSTR + lc] = stB[i];
            }
        }
        __syncthreads();
    }

#pragma unroll
    for (int im = 0; im < 4; im++) {
        int r0 = rowBase + wm * 64 + im * 16 + g;
        int r1 = r0 + 8;
#pragma unroll
        for (int in = 0; in < 8; in++) {
            int c = colBase + wn * 64 + in * 8 + 2 * q;
            float b0 = bias[c], b1 = bias[c + 1];
            float v00 = acc[im][in][0] + b0, v01 = acc[im][in][1] + b1;
            float v10 = acc[im][in][2] + b0, v11 = acc[im][in][3] + b1;
            if (HALF_OUT) {
                __half* C = (__half*)Cout;
                if (r0 < N) *(__half2*)(C + (size_t)r0 * HID + c) = __floats2half2_rn(v00, v01);
                if (r1 < N) *(__half2*)(C + (size_t)r1 * HID + c) = __floats2half2_rn(v10, v11);
            } else {
                float* C = (float*)Cout;
                if (r0 < N) *(float2*)(C + (size_t)r0 * HID + c) = make_float2(v00, v01);
                if (r1 < N) *(float2*)(C + (size_t)r1 * HID + c) = make_float2(v10, v11);
            }
        }
    }
}

// ---------------- fused GAT edge+softmax+aggregate (online softmax, warp/node) ----
// logits[e,h] = att[h] . lrelu(xl[src] + xr[dst]);  alpha = softmax over incoming
// out[n] = ELU( sum_e alpha_e * xl[src_e] + bias )
template <bool HALF_OUT>
__global__ __launch_bounds__(256) void gat_fused_kernel(
    const __half* __restrict__ xl16, const float* __restrict__ xr,
    const float* __restrict__ att, const float* __restrict__ bias,
    void* __restrict__ out)
{
    int node = (blockIdx.x * blockDim.x + threadIdx.x) >> 5;
    if (node >= N_NODES) return;
    int lane = threadIdx.x & 31;
    int dbase = lane * 16;

    // per-lane resident xr chunk + att chunk
    float xrv[16], av[16];
    {
        const float4* pxr = (const float4*)(xr + (size_t)node * HID + dbase);
        const float4* pat = (const float4*)(att + dbase);
#pragma unroll
        for (int j = 0; j < 4; j++) {
            float4 a = pxr[j];
            xrv[j*4+0] = a.x; xrv[j*4+1] = a.y; xrv[j*4+2] = a.z; xrv[j*4+3] = a.w;
            float4 b = pat[j];
            av[j*4+0] = b.x; av[j*4+1] = b.y; av[j*4+2] = b.z; av[j*4+3] = b.w;
        }
    }

    float m = -INFINITY, den = 0.0f;
    float acc[16];
#pragma unroll
    for (int j = 0; j < 16; j++) acc[j] = 0.0f;

    int r0 = d_off[node], r1 = d_off[node + 1];
    for (int i = r0; i < r1; i++) {
        int s = d_csr[i];   // src node id (uniform across warp -> broadcast load)
        const uint4* p = (const uint4*)(xl16 + (size_t)s * HID + dbase);
        uint4 u0 = p[0], u1 = p[1];
        float xlv[16];
        {
            const __half2* h0 = (const __half2*)&u0;
            const __half2* h1 = (const __half2*)&u1;
#pragma unroll
            for (int j = 0; j < 4; j++) {
                float2 f0 = __half22float2(h0[j]);
                xlv[j*2+0] = f0.x; xlv[j*2+1] = f0.y;
                float2 f1 = __half22float2(h1[j]);
                xlv[8+j*2+0] = f1.x; xlv[8+j*2+1] = f1.y;
            }
        }
        // logit partial over this lane's 16 dims
        float part = 0.0f;
#pragma unroll
        for (int j = 0; j < 16; j++) {
            float f = xlv[j] + xrv[j];
            f = (f > 0.0f) ? f : NEG_SLOPE * f;
            part = fmaf(f, av[j], part);
        }
        // reduce across the 4 lanes of this head group
        part += __shfl_xor_sync(0xffffffffu, part, 1);
        part += __shfl_xor_sync(0xffffffffu, part, 2);

        // online softmax update
        float mn  = fmaxf(m, part);
        float fac = __expf(m - mn);      // 0 on first edge (m = -inf)
        float pe  = __expf(part - mn);
        den = den * fac + pe;
#pragma unroll
        for (int j = 0; j < 16; j++) acc[j] = fmaf(acc[j], fac, pe * xlv[j]);
        m = mn;
    }

    float inv = 1.0f / (den + 1e-16f);
    const float* b = bias + dbase;

    if (HALF_OUT) {
        __half2 ov[8];
#pragma unroll
        for (int j = 0; j < 8; j++) {
            float v0 = acc[j*2+0] * inv + b[j*2+0];
            float v1 = acc[j*2+1] * inv + b[j*2+1];
            v0 = (v0 > 0.f) ? v0 : (expf(v0) - 1.0f);
            v1 = (v1 > 0.f) ? v1 : (expf(v1) - 1.0f);
            ov[j] = __floats2half2_rn(v0, v1);
        }
        uint4* o = (uint4*)((__half*)out + (size_t)node * HID + dbase);
        o[0] = *(uint4*)&ov[0];
        o[1] = *(uint4*)&ov[4];
    } else {
        float* o = (float*)out + (size_t)node * HID + dbase;
#pragma unroll
        for (int j4 = 0; j4 < 16; j4 += 4) {
            float4 v;
            float vx;
            vx = acc[j4+0] * inv + b[j4+0]; v.x = (vx > 0.f) ? vx : (expf(vx) - 1.0f);
            vx = acc[j4+1] * inv + b[j4+1]; v.y = (vx > 0.f) ? vx : (expf(vx) - 1.0f);
            vx = acc[j4+2] * inv + b[j4+2]; v.z = (vx > 0.f) ? vx : (expf(vx) - 1.0f);
            vx = acc[j4+3] * inv + b[j4+3]; v.w = (vx > 0.f) ? vx : (expf(vx) - 1.0f);
            *(float4*)(o + j4) = v;
        }
    }
}

// ---------------- pooling: segmented sum (batch is sorted) ----------------
__global__ void pool_seg_kernel(const float* __restrict__ h) {
    int g = blockIdx.x;
    int dim = blockIdx.y * 128 + threadIdx.x;
    int e = d_goff[g + 1];
    float s = 0.0f;
    for (int n = d_goff[g]; n < e; n++) s += h[(size_t)n * HID + dim];
    d_pool[g * HID + dim] = s;
}

// ---------------- head: BN (eval) + FC ----------------
__global__ __launch_bounds__(256) void head_kernel(
    const float* __restrict__ gamma, const float* __restrict__ beta,
    const float* __restrict__ mean,  const float* __restrict__ var,
    const float* __restrict__ Wfc,   const float* __restrict__ bfc,
    float* __restrict__ out)
{
    int g = blockIdx.x;
    int j = threadIdx.x;
    __shared__ float s[HID];
    for (int k = j; k < HID; k += LAT) {
        float v = d_pool[(size_t)g * HID + k];
        s[k] = (v - mean[k]) * rsqrtf(var[k] + BN_EPS) * gamma[k] + beta[k];
    }
    __syncthreads();
    float acc = bfc[j];
    for (int k = 0; k < HID; k++) acc = fmaf(s[k], Wfc[(size_t)k * LAT + j], acc);
    out[(size_t)g * LAT + j] = acc;
}

// ---------------- launch ----------------
extern "C" void kernel_launch(void* const* d_in, const int* in_sizes, int n_in,
                              void* d_out, int out_size)
{
    const float* x      = (const float*)d_in[0];
    const int*   ei     = (const int*)d_in[1];
    const int*   batch  = (const int*)d_in[2];
    const float* Wl0    = (const float*)d_in[3];
    const float* bl0    = (const float*)d_in[4];
    const float* Wr0    = (const float*)d_in[5];
    const float* br0    = (const float*)d_in[6];
    const float* att0   = (const float*)d_in[7];
    const float* bias0  = (const float*)d_in[8];
    const float* Wl1    = (const float*)d_in[9];
    const float* bl1    = (const float*)d_in[10];
    const float* Wr1    = (const float*)d_in[11];
    const float* br1    = (const float*)d_in[12];
    const float* att1   = (const float*)d_in[13];
    const float* bias1  = (const float*)d_in[14];
    const float* bn_g   = (const float*)d_in[15];
    const float* bn_b   = (const float*)d_in[16];
    const float* bn_m   = (const float*)d_in[17];
    const float* bn_v   = (const float*)d_in[18];
    const float* Wfc    = (const float*)d_in[19];
    const float* bfc    = (const float*)d_in[20];
    float* out = (float*)d_out;

    const int* src = ei;
    const int* dst = ei + N_EDGES;

    float *p_xr, *p_h;
    __half *p_xh, *p_xlh, *p_wt0, *p_wt1;
    int *p_deg;
    cudaGetSymbolAddress((void**)&p_xh, d_xh);
    cudaGetSymbolAddress((void**)&p_xlh, d_xlh);
    cudaGetSymbolAddress((void**)&p_xr, d_xr);
    cudaGetSymbolAddress((void**)&p_h, d_h);
    cudaGetSymbolAddress((void**)&p_wt0, d_wt0);
    cudaGetSymbolAddress((void**)&p_wt1, d_wt1);
    cudaGetSymbolAddress((void**)&p_deg, d_deg);

    // ---- CSR build (by dst, storing src) + graph offsets ----
    zero_int_kernel<<<(N_NODES + 255) / 256, 256>>>(p_deg, N_NODES);
    hist_kernel<<<(N_EDGES + 255) / 256, 256>>>(dst);
    scan_kernel<<<1, 1024>>>();
    cursor_kernel<<<(N_NODES + 255) / 256, 256>>>();
    scatter_kernel<<<(N_EDGES + 255) / 256, 256>>>(src, dst);
    goff_kernel<<<1, 256>>>(batch);

    dim3 gemmGrid(HID / GBN, (N_NODES + GBM - 1) / GBM);
    dim3 wtB(32, 8);

    // ---- layer 0 ----
    conv_f2h_kernel<<<(N_NODES * IN_DIM / 4 + 255) / 256, 256>>>(x, p_xh, N_NODES * IN_DIM / 4);
    wtrans_kernel<<<dim3(HID / 32, IN_DIM / 32), wtB>>>(Wl0, p_wt0, IN_DIM);
    wtrans_kernel<<<dim3(HID / 32, IN_DIM / 32), wtB>>>(Wr0, p_wt1, IN_DIM);
    gemm_f16_kernel<true ><<<gemmGrid, 128>>>(p_xh, p_wt0, bl0, p_xlh, N_NODES, IN_DIM);
    gemm_f16_kernel<false><<<gemmGrid, 128>>>(p_xh, p_wt1, br0, p_xr,  N_NODES, IN_DIM);
    gat_fused_kernel<true ><<<(N_NODES * 32 + 255) / 256, 256>>>(p_xlh, p_xr, att0, bias0, p_xh);

    // ---- layer 1 ----
    wtrans_kernel<<<dim3(HID / 32, HID / 32), wtB>>>(Wl1, p_wt0, HID);
    wtrans_kernel<<<dim3(HID / 32, HID / 32), wtB>>>(Wr1, p_wt1, HID);
    gemm_f16_kernel<true ><<<gemmGrid, 128>>>(p_xh, p_wt0, bl1, p_xlh, N_NODES, HID);
    gemm_f16_kernel<false><<<gemmGrid, 128>>>(p_xh, p_wt1, br1, p_xr,  N_NODES, HID);
    gat_fused_kernel<false><<<(N_NODES * 32 + 255) / 256, 256>>>(p_xlh, p_xr, att1, bias1, p_h);

    // ---- pool + head ----
    pool_seg_kernel<<<dim3(N_GRAPHS, HID / 128), 128>>>(p_h);
    head_kernel<<<N_GRAPHS, LAT>>>(bn_g, bn_b, bn_m, bn_v, Wfc, bfc, out);
}

// round 5
// speedup vs baseline: 3.8784x; 1.1043x over previous
#include <cuda_runtime.h>
#include <cuda_fp16.h>
#include <cstdint>
#include <math.h>

#define N_NODES 20000
#define N_EDGES 200000
#define N_GRAPHS 128
#define IN_DIM 256
#define HID 512
#define HEADS 8
#define CH 64
#define LAT 256
#define NEG_SLOPE 0.2f
#define BN_EPS 1e-5f

// ---------------- scratch (static device globals; no allocation) ----------------
__device__ __align__(16) __half d_xh [(size_t)N_NODES * HID];   // GEMM A input (x or h, fp16)
__device__ __align__(16) __half d_xlh[(size_t)N_NODES * HID];   // xl fp16
__device__ __align__(16) float  d_xr [(size_t)N_NODES * HID];   // xr fp32
__device__ __align__(16) float  d_h  [(size_t)N_NODES * HID];   // final layer-1 h (pool input)
__device__ __align__(16) __half d_wt0[(size_t)1024 * 512];      // [Wl0^T; Wr0^T] fp16 [1024, K0]
__device__ __align__(16) __half d_wt1[(size_t)1024 * 512];      // [Wl1^T; Wr1^T] fp16 [1024, K1]
__device__ int   d_deg[N_NODES];
__device__ int   d_off[N_NODES + 1];
__device__ int   d_cursor[N_NODES];
__device__ int   d_csr[N_EDGES];         // stores SRC node id, grouped by dst
__device__ int   d_goff[N_GRAPHS + 1];
__device__ __align__(16) float d_pool[N_GRAPHS * HID];

// ---------------- async / ldmatrix helpers ----------------
__device__ __forceinline__ void cp_async16(uint32_t dst, const void* src, int srcBytes) {
    asm volatile("cp.async.cg.shared.global [%0], [%1], 16, %2;"
                 :: "r"(dst), "l"(src), "r"(srcBytes));
}
__device__ __forceinline__ void cp_commit() {
    asm volatile("cp.async.commit_group;");
}
template <int NREM>
__device__ __forceinline__ void cp_wait() {
    asm volatile("cp.async.wait_group %0;" :: "n"(NREM));
}
__device__ __forceinline__ void ldsm_x4(uint32_t (&r)[4], uint32_t addr) {
    asm volatile("ldmatrix.sync.aligned.m8n8.x4.shared.b16 {%0,%1,%2,%3}, [%4];"
                 : "=r"(r[0]), "=r"(r[1]), "=r"(r[2]), "=r"(r[3]) : "r"(addr));
}

// ---------------- small utility kernels ----------------
__global__ void zero_int_kernel(int* p, int n) {
    int i = blockIdx.x * blockDim.x + threadIdx.x;
    if (i < n) p[i] = 0;
}

__global__ void hist_kernel(const int* __restrict__ dst) {
    int e = blockIdx.x * blockDim.x + threadIdx.x;
    if (e < N_EDGES) atomicAdd(&d_deg[dst[e]], 1);
}

// single-block: exclusive scan of d_deg -> d_off (+cursor), plus goff binary search
__global__ void scan_kernel(const int* __restrict__ batch) {
    __shared__ int sh[1024];
    const int ITEMS = 20;
    int t = threadIdx.x;

    // graph boundaries (independent work, spare parallelism)
    if (t <= N_GRAPHS) {
        int lo = 0, hi = N_NODES;
        while (lo < hi) {
            int mid = (lo + hi) >> 1;
            if (batch[mid] < t) lo = mid + 1; else hi = mid;
        }
        d_goff[t] = lo;
    }

    int base = t * ITEMS;
    int local[ITEMS];
    int s = 0;
#pragma unroll
    for (int i = 0; i < ITEMS; i++) {
        int idx = base + i;
        int v = (idx < N_NODES) ? d_deg[idx] : 0;
        local[i] = s;
        s += v;
    }
    sh[t] = s;
    __syncthreads();
    for (int off = 1; off < 1024; off <<= 1) {
        int v = (t >= off) ? sh[t - off] : 0;
        __syncthreads();
        sh[t] += v;
        __syncthreads();
    }
    int prev = (t > 0) ? sh[t - 1] : 0;
#pragma unroll
    for (int i = 0; i < ITEMS; i++) {
        int idx = base + i;
        if (idx < N_NODES) {
            int v = prev + local[i];
            d_off[idx] = v;
            d_cursor[idx] = v;
        }
    }
    if (t == 1023) d_off[N_NODES] = sh[1023];
}

__global__ void scatter_kernel(const int* __restrict__ src, const int* __restrict__ dst) {
    int e = blockIdx.x * blockDim.x + threadIdx.x;
    if (e < N_EDGES) {
        int p = atomicAdd(&d_cursor[dst[e]], 1);
        d_csr[p] = src[e];
    }
}

// ---------------- fused prep: x->fp16 conversion + 4 weight transposes ----------
// blocks [0,5000): conv;  [5000,5256): layer0 wtrans;  [5256,5768): layer1 wtrans
#define PREP_CONV_BLOCKS 5000
#define PREP_L0_BLOCKS   256
__global__ __launch_bounds__(256) void prep_kernel(
    const float* __restrict__ x,
    const float* __restrict__ Wl0, const float* __restrict__ Wr0,
    const float* __restrict__ Wl1, const float* __restrict__ Wr1)
{
    int b = blockIdx.x;
    if (b < PREP_CONV_BLOCKS) {
        int i = b * 256 + threadIdx.x;          // float4 index
        float4 v = ((const float4*)x)[i];
        __half2* d = (__half2*)d_xh;
        d[i * 2 + 0] = __floats2half2_rn(v.x, v.y);
        d[i * 2 + 1] = __floats2half2_rn(v.z, v.w);
        return;
    }
    __shared__ float tile[32][33];
    const float* W;
    __half* Wt;
    int K, bx, by;
    if (b < PREP_CONV_BLOCKS + PREP_L0_BLOCKS) {
        int m = b - PREP_CONV_BLOCKS;
        int mat = m >> 7;          // 0 = Wl0, 1 = Wr0
        int tb = m & 127;          // 16 x 8 tiles
        bx = tb & 15; by = tb >> 4;
        K = IN_DIM;
        W = mat ? Wr0 : Wl0;
        Wt = d_wt0 + (size_t)mat * 512 * IN_DIM;
    } else {
        int m = b - PREP_CONV_BLOCKS - PREP_L0_BLOCKS;
        int mat = m >> 8;          // 0 = Wl1, 1 = Wr1
        int tb = m & 255;          // 16 x 16 tiles
        bx = tb & 15; by = tb >> 4;
        K = HID;
        W = mat ? Wr1 : Wl1;
        Wt = d_wt1 + (size_t)mat * 512 * HID;
    }
    int n0 = bx * 32;
    int k0 = by * 32;
    int tx = threadIdx.x & 31, ty = threadIdx.x >> 5;   // 32 x 8
#pragma unroll
    for (int j = 0; j < 32; j += 8)
        tile[ty + j][tx] = W[(size_t)(k0 + ty + j) * HID + n0 + tx];
    __syncthreads();
#pragma unroll
    for (int j = 0; j < 32; j += 8)
        Wt[(size_t)(n0 + ty + j) * K + k0 + tx] = __float2half_rn(tile[tx][ty + j]);
}

// ---------------- dual-output fp16 GEMM (cp.async + ldmatrix) --------------------
// A: fp16 [N,K].  Bt: fp16 [1024,K] = [Wl^T ; Wr^T].
// cols 0-511 -> Cl (fp16, +biasL); cols 512-1023 -> Cr (fp32, +biasR).
#define GBM 128
#define HBK 32
#define SSTR 40   // halves per smem row (conflict-free for STS.128 and LDSM)

__global__ __launch_bounds__(128, 2) void gemm_dual_kernel(
    const __half* __restrict__ A, const __half* __restrict__ Bt,
    const float* __restrict__ biasL, const float* __restrict__ biasR,
    __half* __restrict__ Cl, float* __restrict__ Cr,
    int N, int K)
{
    __shared__ __half As[2][GBM * SSTR];
    __shared__ __half Bs[2][GBM * SSTR];

    const int tid  = threadIdx.x;
    const int lane = tid & 31;
    const int warp = tid >> 5;
    const int wm = warp & 1;
    const int wn = warp >> 1;
    const int rowBase = blockIdx.y * GBM;
    const int colBase = blockIdx.x * 128;        // 0..1023 over concat
    const int g = lane >> 2;
    const int q = lane & 3;
    const int nt = K / HBK;

    const uint32_t asb = (uint32_t)__cvta_generic_to_shared(&As[0][0]);
    const uint32_t bsb = (uint32_t)__cvta_generic_to_shared(&Bs[0][0]);
    const uint32_t BUFB = GBM * SSTR * 2;        // bytes per buffer

    const int lr = tid >> 2;          // 0..31
    const int lc = (tid & 3) * 8;     // half offset (16B chunks)

    float acc[4][8][4];
#pragma unroll
    for (int i = 0; i < 4; i++)
#pragma unroll
        for (int j = 0; j < 8; j++)
#pragma unroll
            for (int p = 0; p < 4; p++) acc[i][j][p] = 0.0f;

    // prefetch tile 0
    {
#pragma unroll
        for (int i = 0; i < 4; i++) {
            int r = rowBase + lr + 32 * i;
            int rs = (r < N) ? r : 0;
            cp_async16(asb + ((lr + 32 * i) * SSTR + lc) * 2,
                       A + (size_t)rs * K + lc, (r < N) ? 16 : 0);
            int br = colBase + lr + 32 * i;
            cp_async16(bsb + ((lr + 32 * i) * SSTR + lc) * 2,
                       Bt + (size_t)br * K + lc, 16);
        }
        cp_commit();
    }

    for (int t = 0; t < nt; t++) {
        int buf = t & 1;
        if (t + 1 < nt) {
            int kb = (t + 1) * HBK;
            uint32_t aoff = asb + (buf ^ 1) * BUFB;
            uint32_t boff = bsb + (buf ^ 1) * BUFB;
#pragma unroll
            for (int i = 0; i < 4; i++) {
                int r = rowBase + lr + 32 * i;
                int rs = (r < N) ? r : 0;
                cp_async16(aoff + ((lr + 32 * i) * SSTR + lc) * 2,
                           A + (size_t)rs * K + kb + lc, (r < N) ? 16 : 0);
                int br = colBase + lr + 32 * i;
                cp_async16(boff + ((lr + 32 * i) * SSTR + lc) * 2,
                           Bt + (size_t)br * K + kb + lc, 16);
            }
            cp_commit();
            cp_wait<1>();
        } else {
            cp_wait<0>();
        }
        __syncthreads();

        uint32_t abase = asb + buf * BUFB;
        uint32_t bbase = bsb + buf * BUFB;
        const int arow = wm * 64 + (lane & 15);
        const int ax   = ((lane >> 4) << 3);          // +8 k for matrices 2,3
        const int bnx  = ((lane >> 4) & 1) * 8 + (lane & 7);
        const int bkx  = ((lane >> 3) & 1) * 8;

#pragma unroll
        for (int kk = 0; kk < 2; kk++) {
            const int kh0 = kk * 16;
            uint32_t af[4][4];
#pragma unroll
            for (int im = 0; im < 4; im++)
                ldsm_x4(af[im], abase + ((arow + im * 16) * SSTR + kh0 + ax) * 2);
            uint32_t bf[8][2];
#pragma unroll
            for (int j = 0; j < 8; j += 2) {
                uint32_t r4[4];
                ldsm_x4(r4, bbase + ((wn * 64 + j * 8 + bnx) * SSTR + kh0 + bkx) * 2);
                bf[j][0] = r4[0]; bf[j][1] = r4[1];
                bf[j + 1][0] = r4[2]; bf[j + 1][1] = r4[3];
            }
#pragma unroll
            for (int im = 0; im < 4; im++)
#pragma unroll
                for (int in = 0; in < 8; in++) {
                    asm volatile(
                        "mma.sync.aligned.m16n8k16.row.col.f32.f16.f16.f32 "
                        "{%0,%1,%2,%3}, {%4,%5,%6,%7}, {%8,%9}, {%0,%1,%2,%3};"
                        : "+f"(acc[im][in][0]), "+f"(acc[im][in][1]),
                          "+f"(acc[im][in][2]), "+f"(acc[im][in][3])
                        : "r"(af[im][0]), "r"(af[im][1]), "r"(af[im][2]), "r"(af[im][3]),
                          "r"(bf[in][0]), "r"(bf[in][1]));
                }
        }
        __syncthreads();
    }

    // ---- epilogue ----
    const bool left = (colBase < HID);
#pragma unroll
    for (int im = 0; im < 4; im++) {
        int r0 = rowBase + wm * 64 + im * 16 + g;
        int r1 = r0 + 8;
#pragma unroll
        for (int in = 0; in < 8; in++) {
            int c = colBase + wn * 64 + in * 8 + 2 * q;
            if (left) {
                float b0 = biasL[c], b1 = biasL[c + 1];
                if (r0 < N)
                    *(__half2*)(Cl + (size_t)r0 * HID + c) =
                        __floats2half2_rn(acc[im][in][0] + b0, acc[im][in][1] + b1);
                if (r1 < N)
                    *(__half2*)(Cl + (size_t)r1 * HID + c) =
                        __floats2half2_rn(acc[im][in][2] + b0, acc[im][in][3] + b1);
            } else {
                int cc = c - HID;
                float b0 = biasR[cc], b1 = biasR[cc + 1];
                if (r0 < N)
                    *(float2*)(Cr + (size_t)r0 * HID + cc) =
                        make_float2(acc[im][in][0] + b0, acc[im][in][1] + b1);
                if (r1 < N)
                    *(float2*)(Cr + (size_t)r1 * HID + cc) =
                        make_float2(acc[im][in][2] + b0, acc[im][in][3] + b1);
            }
        }
    }
}

// ---------------- fused GAT edge+softmax+aggregate (online softmax, warp/node) ----
template <bool HALF_OUT>
__global__ __launch_bounds__(256) void gat_fused_kernel(
    const __half* __restrict__ xl16, const float* __restrict__ xr,
    const float* __restrict__ att, const float* __restrict__ bias,
    void* __restrict__ out)
{
    int node = (blockIdx.x * blockDim.x + threadIdx.x) >> 5;
    if (node >= N_NODES) return;
    int lane = threadIdx.x & 31;
    int dbase = lane * 16;

    float xrv[16], av[16];
    {
        const float4* pxr = (const float4*)(xr + (size_t)node * HID + dbase);
        const float4* pat = (const float4*)(att + dbase);
#pragma unroll
        for (int j = 0; j < 4; j++) {
            float4 a = pxr[j];
            xrv[j*4+0] = a.x; xrv[j*4+1] = a.y; xrv[j*4+2] = a.z; xrv[j*4+3] = a.w;
            float4 b = pat[j];
            av[j*4+0] = b.x; av[j*4+1] = b.y; av[j*4+2] = b.z; av[j*4+3] = b.w;
        }
    }

    float m = -INFINITY, den = 0.0f;
    float acc[16];
#pragma unroll
    for (int j = 0; j < 16; j++) acc[j] = 0.0f;

    int r0 = d_off[node], r1 = d_off[node + 1];
    for (int i = r0; i < r1; i++) {
        int s = d_csr[i];
        const uint4* p = (const uint4*)(xl16 + (size_t)s * HID + dbase);
        uint4 u0 = p[0], u1 = p[1];
        float xlv[16];
        {
            const __half2* h0 = (const __half2*)&u0;
            const __half2* h1 = (const __half2*)&u1;
#pragma unroll
            for (int j = 0; j < 4; j++) {
                float2 f0 = __half22float2(h0[j]);
                xlv[j*2+0] = f0.x; xlv[j*2+1] = f0.y;
                float2 f1 = __half22float2(h1[j]);
                xlv[8+j*2+0] = f1.x; xlv[8+j*2+1] = f1.y;
            }
        }
        float part = 0.0f;
#pragma unroll
        for (int j = 0; j < 16; j++) {
            float f = xlv[j] + xrv[j];
            f = (f > 0.0f) ? f : NEG_SLOPE * f;
            part = fmaf(f, av[j], part);
        }
        part += __shfl_xor_sync(0xffffffffu, part, 1);
        part += __shfl_xor_sync(0xffffffffu, part, 2);

        float mn  = fmaxf(m, part);
        float fac = __expf(m - mn);
        float pe  = __expf(part - mn);
        den = den * fac + pe;
#pragma unroll
        for (int j = 0; j < 16; j++) acc[j] = fmaf(acc[j], fac, pe * xlv[j]);
        m = mn;
    }

    float inv = 1.0f / (den + 1e-16f);
    const float* b = bias + dbase;

    if (HALF_OUT) {
        __half2 ov[8];
#pragma unroll
        for (int j = 0; j < 8; j++) {
            float v0 = acc[j*2+0] * inv + b[j*2+0];
            float v1 = acc[j*2+1] * inv + b[j*2+1];
            v0 = (v0 > 0.f) ? v0 : (expf(v0) - 1.0f);
            v1 = (v1 > 0.f) ? v1 : (expf(v1) - 1.0f);
            ov[j] = __floats2half2_rn(v0, v1);
        }
        uint4* o = (uint4*)((__half*)out + (size_t)node * HID + dbase);
        o[0] = *(uint4*)&ov[0];
        o[1] = *(uint4*)&ov[4];
    } else {
        float* o = (float*)out + (size_t)node * HID + dbase;
#pragma unroll
        for (int j4 = 0; j4 < 16; j4 += 4) {
            float4 v;
            float vx;
            vx = acc[j4+0] * inv + b[j4+0]; v.x = (vx > 0.f) ? vx : (expf(vx) - 1.0f);
            vx = acc[j4+1] * inv + b[j4+1]; v.y = (vx > 0.f) ? vx : (expf(vx) - 1.0f);
            vx = acc[j4+2] * inv + b[j4+2]; v.z = (vx > 0.f) ? vx : (expf(vx) - 1.0f);
            vx = acc[j4+3] * inv + b[j4+3]; v.w = (vx > 0.f) ? vx : (expf(vx) - 1.0f);
            *(float4*)(o + j4) = v;
        }
    }
}

// ---------------- pooling: segmented sum (batch is sorted) ----------------
__global__ void pool_seg_kernel(const float* __restrict__ h) {
    int g = blockIdx.x;
    int dim = blockIdx.y * 128 + threadIdx.x;
    int e = d_goff[g + 1];
    float s = 0.0f;
    for (int n = d_goff[g]; n < e; n++) s += h[(size_t)n * HID + dim];
    d_pool[g * HID + dim] = s;
}

// ---------------- head: BN (eval) + FC ----------------
__global__ __launch_bounds__(256) void head_kernel(
    const float* __restrict__ gamma, const float* __restrict__ beta,
    const float* __restrict__ mean,  const float* __restrict__ var,
    const float* __restrict__ Wfc,   const float* __restrict__ bfc,
    float* __restrict__ out)
{
    int g = blockIdx.x;
    int j = threadIdx.x;
    __shared__ float s[HID];
    for (int k = j; k < HID; k += LAT) {
        float v = d_pool[(size_t)g * HID + k];
        s[k] = (v - mean[k]) * rsqrtf(var[k] + BN_EPS) * gamma[k] + beta[k];
    }
    __syncthreads();
    float acc = bfc[j];
    for (int k = 0; k < HID; k++) acc = fmaf(s[k], Wfc[(size_t)k * LAT + j], acc);
    out[(size_t)g * LAT + j] = acc;
}

// ---------------- launch ----------------
extern "C" void kernel_launch(void* const* d_in, const int* in_sizes, int n_in,
                              void* d_out, int out_size)
{
    const float* x      = (const float*)d_in[0];
    const int*   ei     = (const int*)d_in[1];
    const int*   batch  = (const int*)d_in[2];
    const float* Wl0    = (const float*)d_in[3];
    const float* bl0    = (const float*)d_in[4];
    const float* Wr0    = (const float*)d_in[5];
    const float* br0    = (const float*)d_in[6];
    const float* att0   = (const float*)d_in[7];
    const float* bias0  = (const float*)d_in[8];
    const float* Wl1    = (const float*)d_in[9];
    const float* bl1    = (const float*)d_in[10];
    const float* Wr1    = (const float*)d_in[11];
    const float* br1    = (const float*)d_in[12];
    const float* att1   = (const float*)d_in[13];
    const float* bias1  = (const float*)d_in[14];
    const float* bn_g   = (const float*)d_in[15];
    const float* bn_b   = (const float*)d_in[16];
    const float* bn_m   = (const float*)d_in[17];
    const float* bn_v   = (const float*)d_in[18];
    const float* Wfc    = (const float*)d_in[19];
    const float* bfc    = (const float*)d_in[20];
    float* out = (float*)d_out;

    const int* src = ei;
    const int* dst = ei + N_EDGES;

    float *p_xr, *p_h;
    __half *p_xh, *p_xlh, *p_wt0, *p_wt1;
    int *p_deg;
    cudaGetSymbolAddress((void**)&p_xh, d_xh);
    cudaGetSymbolAddress((void**)&p_xlh, d_xlh);
    cudaGetSymbolAddress((void**)&p_xr, d_xr);
    cudaGetSymbolAddress((void**)&p_h, d_h);
    cudaGetSymbolAddress((void**)&p_wt0, d_wt0);
    cudaGetSymbolAddress((void**)&p_wt1, d_wt1);
    cudaGetSymbolAddress((void**)&p_deg, d_deg);

    // ---- prep (conv + all weight transposes) + CSR build ----
    prep_kernel<<<PREP_CONV_BLOCKS + PREP_L0_BLOCKS + 512, 256>>>(x, Wl0, Wr0, Wl1, Wr1);
    zero_int_kernel<<<(N_NODES + 255) / 256, 256>>>(p_deg, N_NODES);
    hist_kernel<<<(N_EDGES + 255) / 256, 256>>>(dst);
    scan_kernel<<<1, 1024>>>(batch);
    scatter_kernel<<<(N_EDGES + 255) / 256, 256>>>(src, dst);

    dim3 gemmGrid(8, (N_NODES + GBM - 1) / GBM);

    // ---- layer 0 ----
    gemm_dual_kernel<<<gemmGrid, 128>>>(p_xh, p_wt0, bl0, br0, p_xlh, p_xr, N_NODES, IN_DIM);
    gat_fused_kernel<true ><<<(N_NODES * 32 + 255) / 256, 256>>>(p_xlh, p_xr, att0, bias0, p_xh);

    // ---- layer 1 ----
    gemm_dual_kernel<<<gemmGrid, 128>>>(p_xh, p_wt1, bl1, br1, p_xlh, p_xr, N_NODES, HID);
    gat_fused_kernel<false><<<(N_NODES * 32 + 255) / 256, 256>>>(p_xlh, p_xr, att1, bias1, p_h);

    // ---- pool + head ----
    pool_seg_kernel<<<dim3(N_GRAPHS, HID / 128), 128>>>(p_h);
    head_kernel<<<N_GRAPHS, LAT>>>(bn_g, bn_b, bn_m, bn_v, Wfc, bfc, out);
}